// round 1
// baseline (speedup 1.0000x reference)
#include <cuda_runtime.h>
#include <math.h>

#define TT    2048      // tokens = B*S
#define HD    1024      // hidden
#define NH    8
#define SEQ   1024
#define NEXP  8
#define SCALE_F 0.07216878364870322f   // 192^-0.5

// ---------------- scratch (no runtime allocation allowed) ----------------
__device__ float g_wqp [1024*1024];
__device__ float g_h   [TT*HD];
__device__ float g_q   [TT*1024];
__device__ float g_kv  [TT*2048];
__device__ float g_attn[TT*1024];
__device__ float g_x2  [TT*HD];
__device__ float g_h2  [TT*HD];
__device__ float g_gu  [TT*2048];
__device__ float g_act [TT*1024];
__device__ float g_he  [2*TT*1024];
__device__ float g_ybuf[2*TT*1024];
__device__ float g_topw[2*TT];
__device__ float g_pscale[2*TT];
__device__ int   g_topi[2*TT];
__device__ int   g_ptok[2*TT];
__device__ int   g_pdst[2*TT];
__device__ int   g_cnt [NEXP];
__device__ int   g_off [NEXP];

// ---------------- pack Wq: keep only nope dims (h*192+d, d<128) ----------
__global__ void pack_wq_kernel(const float* __restrict__ Wq, float* __restrict__ Wqp) {
    int r = blockIdx.x;                // 0..1023 packed row
    int h = r >> 7, d = r & 127;
    const float4* src = (const float4*)(Wq + (size_t)(h*192 + d) * HD);
    float4*       dst = (float4*)(Wqp + (size_t)r * HD);
    int i = threadIdx.x;               // 256 threads, 256 float4 per row
    dst[i] = src[i];
}

// ---------------- rmsnorm ----------------
__global__ void rmsnorm_kernel(const float* __restrict__ x, const float* __restrict__ w,
                               float* __restrict__ out) {
    int t = blockIdx.x;
    const float* xr = x + (size_t)t * HD;
    float ss = 0.f;
    for (int i = threadIdx.x; i < HD; i += 256) { float v = xr[i]; ss += v * v; }
    __shared__ float red[256];
    red[threadIdx.x] = ss; __syncthreads();
    for (int o = 128; o > 0; o >>= 1) {
        if (threadIdx.x < o) red[threadIdx.x] += red[threadIdx.x + o];
        __syncthreads();
    }
    float inv = rsqrtf(red[0] * (1.f / HD) + 1e-6f);
    for (int i = threadIdx.x; i < HD; i += 256)
        out[(size_t)t * HD + i] = xr[i] * inv * w[i];
}

// ---------------- shared GEMM core: C(64x64) tile, A[M,K] x B[N,K]^T ------
__device__ __forceinline__ void gemm_core(const float* __restrict__ Arow,
                                          const float* __restrict__ Brow,
                                          int K, float (*As)[68], float (*Bs)[68],
                                          float acc[4][4]) {
    int tid = threadIdx.x;
    int tx = tid & 15, ty = tid >> 4;
    int lr = tid >> 2, lk = (tid & 3) << 2;
    (void)lr; (void)lk;
    float4 a4 = *(const float4*)(Arow);
    float4 b4 = *(const float4*)(Brow);
    for (int k0 = 0; k0 < K; k0 += 16) {
        int slr = tid >> 2, slk = (tid & 3) << 2;
        As[slk+0][slr] = a4.x; As[slk+1][slr] = a4.y; As[slk+2][slr] = a4.z; As[slk+3][slr] = a4.w;
        Bs[slk+0][slr] = b4.x; Bs[slk+1][slr] = b4.y; Bs[slk+2][slr] = b4.z; Bs[slk+3][slr] = b4.w;
        __syncthreads();
        if (k0 + 16 < K) {
            a4 = *(const float4*)(Arow + k0 + 16);
            b4 = *(const float4*)(Brow + k0 + 16);
        }
#pragma unroll
        for (int kk = 0; kk < 16; kk++) {
            float4 av = *(const float4*)&As[kk][ty << 2];
            float4 bv = *(const float4*)&Bs[kk][tx << 2];
            acc[0][0] += av.x*bv.x; acc[0][1] += av.x*bv.y; acc[0][2] += av.x*bv.z; acc[0][3] += av.x*bv.w;
            acc[1][0] += av.y*bv.x; acc[1][1] += av.y*bv.y; acc[1][2] += av.y*bv.z; acc[1][3] += av.y*bv.w;
            acc[2][0] += av.z*bv.x; acc[2][1] += av.z*bv.y; acc[2][2] += av.z*bv.z; acc[2][3] += av.z*bv.w;
            acc[3][0] += av.w*bv.x; acc[3][1] += av.w*bv.y; acc[3][2] += av.w*bv.z; acc[3][3] += av.w*bv.w;
        }
        __syncthreads();
    }
}

// EPI: 0 = plain store, 1 = store + residual R
template<int EPI>
__global__ void __launch_bounds__(256) gemm_nt(const float* __restrict__ A,
                                               const float* __restrict__ B,
                                               float* __restrict__ C,
                                               const float* __restrict__ R,
                                               int K, int lda, int ldb, int ldc) {
    __shared__ float As[16][68], Bs[16][68];
    int bm = blockIdx.y << 6, bn = blockIdx.x << 6;
    int tid = threadIdx.x, tx = tid & 15, ty = tid >> 4;
    int lr = tid >> 2, lk = (tid & 3) << 2;
    float acc[4][4] = {};
    gemm_core(A + (size_t)(bm + lr) * lda + lk,
              B + (size_t)(bn + lr) * ldb + lk, K, As, Bs, acc);
#pragma unroll
    for (int i = 0; i < 4; i++) {
        int m = bm + (ty << 2) + i;
        float4 v = make_float4(acc[i][0], acc[i][1], acc[i][2], acc[i][3]);
        size_t o = (size_t)m * ldc + bn + (tx << 2);
        if (EPI == 1) {
            float4 r4 = *(const float4*)(R + o);
            v.x += r4.x; v.y += r4.y; v.z += r4.z; v.w += r4.w;
        }
        *(float4*)(C + o) = v;
    }
}

// ---------------- flash attention (causal, d=128, fp32) -------------------
// q: [T, NH*128] nope-packed; kv: [T, 2048] (k cols 0..1023, v cols 1024..2047)
#define ATTN_SMEM_FLOATS 22016
__global__ void __launch_bounds__(256) attn_kernel(const float* __restrict__ q,
                                                   const float* __restrict__ kv,
                                                   float* __restrict__ o) {
    extern __shared__ float sm[];
    float* Qt   = sm;                   // [128][64] transposed
    float* KV   = sm + 8192;            // K stride 129 / V stride 132 (reused)
    float* Ps   = sm + 8192 + 8448;     // [64][65]
    float* red  = Ps + 64 * 65;         // [64][16]
    float* mrow = red + 1024;
    float* lrow = mrow + 64;
    float* rsb  = lrow + 64;

    const int qt = blockIdx.x, head = blockIdx.y, b = blockIdx.z;
    const int tid = threadIdx.x, tx = tid & 15, ty = tid >> 4;
    const int qbase = qt << 6;
    const size_t tok0 = (size_t)b * SEQ;
    const int hoff = head << 7;

    // load Q tile transposed (once)
#pragma unroll
    for (int it = 0; it < 8; it++) {
        int lin = tid + (it << 8);
        int r = lin >> 5, d0 = (lin & 31) << 2;
        float4 v = *(const float4*)(q + (tok0 + qbase + r) * 1024 + hoff + d0);
        Qt[(d0+0)*64 + r] = v.x; Qt[(d0+1)*64 + r] = v.y;
        Qt[(d0+2)*64 + r] = v.z; Qt[(d0+3)*64 + r] = v.w;
    }
    if (tid < 64) { mrow[tid] = -1e30f; lrow[tid] = 0.f; }

    float acc[4][8];
#pragma unroll
    for (int i = 0; i < 4; i++)
#pragma unroll
        for (int j = 0; j < 8; j++) acc[i][j] = 0.f;

    for (int kt = 0; kt <= qt; kt++) {
        __syncthreads();                           // KV buffer safe to overwrite
        // K tile -> KV (row-major, stride 129)
#pragma unroll
        for (int it = 0; it < 8; it++) {
            int lin = tid + (it << 8);
            int c = lin >> 5, d0 = (lin & 31) << 2;
            float4 v = *(const float4*)(kv + (tok0 + (kt<<6) + c) * 2048 + hoff + d0);
            float* dst = KV + c * 129 + d0;
            dst[0]=v.x; dst[1]=v.y; dst[2]=v.z; dst[3]=v.w;
        }
        __syncthreads();
        // S = Q K^T
        float s[4][4] = {};
        const float* qb = Qt + (ty << 2);
        const float* kb = KV + (tx << 2) * 129;
#pragma unroll 4
        for (int d = 0; d < 128; d++) {
            float4 av = *(const float4*)(qb + d * 64);
            float b0 = kb[d], b1 = kb[129 + d], b2 = kb[258 + d], b3 = kb[387 + d];
            s[0][0]+=av.x*b0; s[0][1]+=av.x*b1; s[0][2]+=av.x*b2; s[0][3]+=av.x*b3;
            s[1][0]+=av.y*b0; s[1][1]+=av.y*b1; s[1][2]+=av.y*b2; s[1][3]+=av.y*b3;
            s[2][0]+=av.z*b0; s[2][1]+=av.z*b1; s[2][2]+=av.z*b2; s[2][3]+=av.z*b3;
            s[3][0]+=av.w*b0; s[3][1]+=av.w*b1; s[3][2]+=av.w*b2; s[3][3]+=av.w*b3;
        }
#pragma unroll
        for (int i = 0; i < 4; i++)
#pragma unroll
            for (int j = 0; j < 4; j++) s[i][j] *= SCALE_F;
        if (kt == qt) {
#pragma unroll
            for (int i = 0; i < 4; i++)
#pragma unroll
                for (int j = 0; j < 4; j++)
                    if ((kt<<6) + (tx<<2) + j > qbase + (ty<<2) + i) s[i][j] = -1e30f;
        }
#pragma unroll
        for (int i = 0; i < 4; i++) {
            float mx = fmaxf(fmaxf(s[i][0], s[i][1]), fmaxf(s[i][2], s[i][3]));
            red[((ty<<2)+i)*16 + tx] = mx;
        }
        __syncthreads();
        // V tile -> KV (stride 132) while row-owners update stats
#pragma unroll
        for (int it = 0; it < 8; it++) {
            int lin = tid + (it << 8);
            int c = lin >> 5, d0 = (lin & 31) << 2;
            float4 v = *(const float4*)(kv + (tok0 + (kt<<6) + c) * 2048 + 1024 + hoff + d0);
            float* dst = KV + c * 132 + d0;
            dst[0]=v.x; dst[1]=v.y; dst[2]=v.z; dst[3]=v.w;
        }
        if (tid < 64) {
            float mx = mrow[tid];
#pragma unroll
            for (int k = 0; k < 16; k++) mx = fmaxf(mx, red[tid*16 + k]);
            rsb[tid]  = expf(mrow[tid] - mx);
            mrow[tid] = mx;
        }
        __syncthreads();
        // P, rescale acc, partial sums
#pragma unroll
        for (int i = 0; i < 4; i++) {
            int r = (ty << 2) + i;
            float m = mrow[r], f = rsb[r];
            float p0 = expf(s[i][0]-m), p1 = expf(s[i][1]-m);
            float p2 = expf(s[i][2]-m), p3 = expf(s[i][3]-m);
            Ps[((tx<<2)+0)*65 + r] = p0; Ps[((tx<<2)+1)*65 + r] = p1;
            Ps[((tx<<2)+2)*65 + r] = p2; Ps[((tx<<2)+3)*65 + r] = p3;
            red[r*16 + tx] = p0 + p1 + p2 + p3;
#pragma unroll
            for (int j = 0; j < 8; j++) acc[i][j] *= f;
        }
        __syncthreads();
        if (tid < 64) {
            float sum = 0.f;
#pragma unroll
            for (int k = 0; k < 16; k++) sum += red[tid*16 + k];
            lrow[tid] = lrow[tid] * rsb[tid] + sum;
        }
        // PV accumulate
        const float* pb = Ps + (ty << 2);
        const float* vb = KV + (tx << 3);
#pragma unroll 2
        for (int kk = 0; kk < 64; kk++) {
            float4 v0 = *(const float4*)(vb + kk*132);
            float4 v1 = *(const float4*)(vb + kk*132 + 4);
            float p0 = pb[kk*65+0], p1 = pb[kk*65+1], p2 = pb[kk*65+2], p3 = pb[kk*65+3];
            acc[0][0]+=p0*v0.x; acc[0][1]+=p0*v0.y; acc[0][2]+=p0*v0.z; acc[0][3]+=p0*v0.w;
            acc[0][4]+=p0*v1.x; acc[0][5]+=p0*v1.y; acc[0][6]+=p0*v1.z; acc[0][7]+=p0*v1.w;
            acc[1][0]+=p1*v0.x; acc[1][1]+=p1*v0.y; acc[1][2]+=p1*v0.z; acc[1][3]+=p1*v0.w;
            acc[1][4]+=p1*v1.x; acc[1][5]+=p1*v1.y; acc[1][6]+=p1*v1.z; acc[1][7]+=p1*v1.w;
            acc[2][0]+=p2*v0.x; acc[2][1]+=p2*v0.y; acc[2][2]+=p2*v0.z; acc[2][3]+=p2*v0.w;
            acc[2][4]+=p2*v1.x; acc[2][5]+=p2*v1.y; acc[2][6]+=p2*v1.z; acc[2][7]+=p2*v1.w;
            acc[3][0]+=p3*v0.x; acc[3][1]+=p3*v0.y; acc[3][2]+=p3*v0.z; acc[3][3]+=p3*v0.w;
            acc[3][4]+=p3*v1.x; acc[3][5]+=p3*v1.y; acc[3][6]+=p3*v1.z; acc[3][7]+=p3*v1.w;
        }
    }
    __syncthreads();
#pragma unroll
    for (int i = 0; i < 4; i++) {
        int r = (ty << 2) + i;
        float inv = 1.f / lrow[r];
        float* op = o + (tok0 + qbase + r) * 1024 + hoff + (tx << 3);
        *(float4*)op     = make_float4(acc[i][0]*inv, acc[i][1]*inv, acc[i][2]*inv, acc[i][3]*inv);
        *(float4*)(op+4) = make_float4(acc[i][4]*inv, acc[i][5]*inv, acc[i][6]*inv, acc[i][7]*inv);
    }
}

// ---------------- MoE gate: logits, softmax, top-2, renorm ---------------
__global__ void gate_kernel(const float* __restrict__ h2, const float* __restrict__ gw) {
    int t = blockIdx.x;
    int w = threadIdx.x >> 5, lane = threadIdx.x & 31;
    const float* xr = h2 + (size_t)t * HD;
    const float* gr = gw + (size_t)w * HD;
    float ss = 0.f;
    for (int i = lane; i < HD; i += 32) ss += xr[i] * gr[i];
#pragma unroll
    for (int o = 16; o > 0; o >>= 1) ss += __shfl_down_sync(0xffffffffu, ss, o);
    __shared__ float lg[NEXP];
    if (lane == 0) lg[w] = ss;
    __syncthreads();
    if (threadIdx.x == 0) {
        int i1 = 0;
#pragma unroll
        for (int e = 1; e < NEXP; e++) if (lg[e] > lg[i1]) i1 = e;
        int i2 = (i1 == 0) ? 1 : 0;
#pragma unroll
        for (int e = 0; e < NEXP; e++) if (e != i1 && lg[e] > lg[i2]) i2 = e;
        float e1 = expf(lg[i1] - lg[i1]);              // = 1
        float e2 = expf(lg[i2] - lg[i1]);
        float inv = 1.f / (e1 + e2);
        g_topi[2*t]   = i1; g_topw[2*t]   = e1 * inv;
        g_topi[2*t+1] = i2; g_topw[2*t+1] = e2 * inv;
    }
}

// ---------------- deterministic expert grouping --------------------------
__global__ void route_group_kernel() {
    __shared__ int hist[NEXP * 256];
    __shared__ int soff[NEXP + 1];
    __shared__ int stot[NEXP];
    int tid = threadIdx.x;
    int t0 = tid * 8;                        // 2048/256 = 8 tokens per thread
    int lc[NEXP];
#pragma unroll
    for (int e = 0; e < NEXP; e++) lc[e] = 0;
    for (int t = t0; t < t0 + 8; t++) {
        lc[g_topi[2*t]]++; lc[g_topi[2*t+1]]++;
    }
#pragma unroll
    for (int e = 0; e < NEXP; e++) hist[e * 256 + tid] = lc[e];
    __syncthreads();
    if (tid < NEXP) {
        int a = 0;
        for (int i = 0; i < 256; i++) { int v = hist[tid*256+i]; hist[tid*256+i] = a; a += v; }
        stot[tid] = a;
    }
    __syncthreads();
    if (tid == 0) {
        int a = 0;
        for (int e = 0; e < NEXP; e++) { soff[e] = a; g_off[e] = a; g_cnt[e] = stot[e]; a += stot[e]; }
        soff[NEXP] = a;
    }
    __syncthreads();
    int pos[NEXP];
#pragma unroll
    for (int e = 0; e < NEXP; e++) pos[e] = soff[e] + hist[e * 256 + tid];
    for (int t = t0; t < t0 + 8; t++) {
        for (int s2 = 0; s2 < 2; s2++) {
            int e = g_topi[2*t + s2];
            int p = pos[e]++;
            g_ptok[p] = t; g_pdst[p] = 2*t + s2; g_pscale[p] = g_topw[2*t + s2];
        }
    }
}

// ---------------- grouped expert GEMMs -----------------------------------
// stage 1: he[p,:] = silu( h2[tok(p),:] @ w1[e]^T )
__global__ void __launch_bounds__(256) expert_gemm1(const float* __restrict__ h2,
                                                    const float* __restrict__ w1) {
    int e = blockIdx.z;
    int cnt = g_cnt[e]; if (cnt == 0) return;
    int bm = blockIdx.y << 6; if (bm >= cnt) return;
    int off = g_off[e];
    int bn = blockIdx.x << 6;
    __shared__ float As[16][68], Bs[16][68];
    int tid = threadIdx.x, tx = tid & 15, ty = tid >> 4;
    int lr = tid >> 2, lk = (tid & 3) << 2;
    int gr = bm + lr; if (gr >= cnt) gr = cnt - 1;
    int tok = g_ptok[off + gr];
    float acc[4][4] = {};
    gemm_core(h2 + (size_t)tok * HD + lk,
              w1 + (size_t)e * 1024 * HD + (size_t)(bn + lr) * HD + lk,
              HD, As, Bs, acc);
#pragma unroll
    for (int i = 0; i < 4; i++) {
        int m = bm + (ty << 2) + i;
        if (m < cnt) {
            float4 v;
            v.x = acc[i][0] / (1.f + expf(-acc[i][0]));
            v.y = acc[i][1] / (1.f + expf(-acc[i][1]));
            v.z = acc[i][2] / (1.f + expf(-acc[i][2]));
            v.w = acc[i][3] / (1.f + expf(-acc[i][3]));
            *(float4*)(g_he + (size_t)(off + m) * 1024 + bn + (tx << 2)) = v;
        }
    }
}

// stage 2: ybuf[dst(p),:] = scale(p) * ( he[p,:] @ w2[e]^T )
__global__ void __launch_bounds__(256) expert_gemm2(const float* __restrict__ w2) {
    int e = blockIdx.z;
    int cnt = g_cnt[e]; if (cnt == 0) return;
    int bm = blockIdx.y << 6; if (bm >= cnt) return;
    int off = g_off[e];
    int bn = blockIdx.x << 6;
    __shared__ float As[16][68], Bs[16][68];
    int tid = threadIdx.x, tx = tid & 15, ty = tid >> 4;
    int lr = tid >> 2, lk = (tid & 3) << 2;
    int gr = bm + lr; if (gr >= cnt) gr = cnt - 1;
    float acc[4][4] = {};
    gemm_core(g_he + (size_t)(off + gr) * 1024 + lk,
              w2 + (size_t)e * HD * 1024 + (size_t)(bn + lr) * 1024 + lk,
              1024, As, Bs, acc);
#pragma unroll
    for (int i = 0; i < 4; i++) {
        int m = bm + (ty << 2) + i;
        if (m < cnt) {
            int p = off + m;
            int dst = g_pdst[p];
            float sc = g_pscale[p];
            float4 v = make_float4(acc[i][0]*sc, acc[i][1]*sc, acc[i][2]*sc, acc[i][3]*sc);
            *(float4*)(g_ybuf + (size_t)dst * HD + bn + (tx << 2)) = v;
        }
    }
}

// ---------------- elementwise tails --------------------------------------
__global__ void swiglu_kernel(const float* __restrict__ gu, float* __restrict__ act) {
    int t = blockIdx.x, i = threadIdx.x;     // 256 threads, float4 each
    float4 g = *(const float4*)(gu + (size_t)t*2048 + 4*i);
    float4 u = *(const float4*)(gu + (size_t)t*2048 + 1024 + 4*i);
    float4 r;
    r.x = g.x / (1.f + expf(-g.x)) * u.x;
    r.y = g.y / (1.f + expf(-g.y)) * u.y;
    r.z = g.z / (1.f + expf(-g.z)) * u.z;
    r.w = g.w / (1.f + expf(-g.w)) * u.w;
    *(float4*)(act + (size_t)t*HD + 4*i) = r;
}

__global__ void add_routed_kernel(float* __restrict__ out) {
    int t = blockIdx.x, i = threadIdx.x;
    float4 a = *(const float4*)(out + (size_t)t*HD + 4*i);
    float4 y0 = *(const float4*)(g_ybuf + (size_t)(2*t)*HD + 4*i);
    float4 y1 = *(const float4*)(g_ybuf + (size_t)(2*t+1)*HD + 4*i);
    a.x += y0.x + y1.x; a.y += y0.y + y1.y; a.z += y0.z + y1.z; a.w += y0.w + y1.w;
    *(float4*)(out + (size_t)t*HD + 4*i) = a;
}

// ---------------- launch ---------------------------------------------------
extern "C" void kernel_launch(void* const* d_in, const int* in_sizes, int n_in,
                              void* d_out, int out_size) {
    const float* x    = (const float*)d_in[0];
    const float* ln1  = (const float*)d_in[2];
    const float* ln2  = (const float*)d_in[3];
    const float* Wq   = (const float*)d_in[4];
    const float* Wkv  = (const float*)d_in[5];
    const float* Wo   = (const float*)d_in[6];
    const float* gate = (const float*)d_in[7];
    const float* w1   = (const float*)d_in[8];
    const float* w2   = (const float*)d_in[9];
    const float* sgu  = (const float*)d_in[10];
    const float* sdwn = (const float*)d_in[11];
    float* out = (float*)d_out;

    float *p_wqp, *p_h, *p_q, *p_kv, *p_attn, *p_x2, *p_h2, *p_gu, *p_act;
    cudaGetSymbolAddress((void**)&p_wqp,  g_wqp);
    cudaGetSymbolAddress((void**)&p_h,    g_h);
    cudaGetSymbolAddress((void**)&p_q,    g_q);
    cudaGetSymbolAddress((void**)&p_kv,   g_kv);
    cudaGetSymbolAddress((void**)&p_attn, g_attn);
    cudaGetSymbolAddress((void**)&p_x2,   g_x2);
    cudaGetSymbolAddress((void**)&p_h2,   g_h2);
    cudaGetSymbolAddress((void**)&p_gu,   g_gu);
    cudaGetSymbolAddress((void**)&p_act,  g_act);

    const int ATTN_SMEM = ATTN_SMEM_FLOATS * 4;
    cudaFuncSetAttribute(attn_kernel, cudaFuncAttributeMaxDynamicSharedMemorySize, ATTN_SMEM);

    // attention block
    pack_wq_kernel<<<1024, 256>>>(Wq, p_wqp);
    rmsnorm_kernel<<<TT, 256>>>(x, ln1, p_h);
    gemm_nt<0><<<dim3(16, 32), 256>>>(p_h, p_wqp, p_q,  nullptr, 1024, 1024, 1024, 1024);
    gemm_nt<0><<<dim3(32, 32), 256>>>(p_h, Wkv,   p_kv, nullptr, 1024, 1024, 1024, 2048);
    attn_kernel<<<dim3(16, NH, 2), 256, ATTN_SMEM>>>(p_q, p_kv, p_attn);
    gemm_nt<1><<<dim3(16, 32), 256>>>(p_attn, Wo, p_x2, x, 1024, 1024, 1024, 1024);

    // MoE block
    rmsnorm_kernel<<<TT, 256>>>(p_x2, ln2, p_h2);
    gate_kernel<<<TT, 256>>>(p_h2, gate);
    route_group_kernel<<<1, 256>>>();
    expert_gemm1<<<dim3(16, 32, NEXP), 256>>>(p_h2, w1);
    expert_gemm2<<<dim3(16, 32, NEXP), 256>>>(w2);

    // shared expert
    gemm_nt<0><<<dim3(32, 32), 256>>>(p_h2, sgu, p_gu, nullptr, 1024, 1024, 1024, 2048);
    swiglu_kernel<<<TT, 256>>>(p_gu, p_act);
    gemm_nt<1><<<dim3(16, 32), 256>>>(p_act, sdwn, out, p_x2, 1024, 1024, 1024, 1024);

    // combine routed experts
    add_routed_kernel<<<TT, 256>>>(out);
}

// round 2
// speedup vs baseline: 1.3590x; 1.3590x over previous
#include <cuda_runtime.h>
#include <math.h>

#define TT    2048      // tokens = B*S
#define HD    1024      // hidden
#define NH    8
#define SEQ   1024
#define NEXP  8
#define SCALE_F 0.07216878364870322f   // 192^-0.5

// ---------------- scratch (no runtime allocation allowed) ----------------
__device__ float g_wqp [1024*1024];
__device__ float g_h   [TT*HD];
__device__ float g_q   [TT*1024];
__device__ float g_kv  [TT*2048];
__device__ float g_attn[TT*1024];
__device__ float g_x2  [TT*HD];
__device__ float g_h2  [TT*HD];
__device__ float g_gu  [TT*2048];
__device__ float g_act [TT*1024];
__device__ float g_he  [2*TT*1024];
__device__ float g_ybuf[2*TT*1024];
__device__ float g_topw[2*TT];
__device__ float g_pscale[2*TT];
__device__ int   g_topi[2*TT];
__device__ int   g_ptok[2*TT];
__device__ int   g_pdst[2*TT];
__device__ int   g_cnt [NEXP];
__device__ int   g_off [NEXP];

// ---------------- pack Wq: keep only nope dims ----------
__global__ void pack_wq_kernel(const float* __restrict__ Wq, float* __restrict__ Wqp) {
    int r = blockIdx.x;
    int h = r >> 7, d = r & 127;
    const float4* src = (const float4*)(Wq + (size_t)(h*192 + d) * HD);
    float4*       dst = (float4*)(Wqp + (size_t)r * HD);
    dst[threadIdx.x] = src[threadIdx.x];
}

// ---------------- rmsnorm ----------------
__global__ void rmsnorm_kernel(const float* __restrict__ x, const float* __restrict__ w,
                               float* __restrict__ out) {
    int t = blockIdx.x;
    const float* xr = x + (size_t)t * HD;
    float ss = 0.f;
    for (int i = threadIdx.x; i < HD; i += 256) { float v = xr[i]; ss += v * v; }
    __shared__ float red[256];
    red[threadIdx.x] = ss; __syncthreads();
    for (int o = 128; o > 0; o >>= 1) {
        if (threadIdx.x < o) red[threadIdx.x] += red[threadIdx.x + o];
        __syncthreads();
    }
    float inv = rsqrtf(red[0] * (1.f / HD) + 1e-6f);
    for (int i = threadIdx.x; i < HD; i += 256)
        out[(size_t)t * HD + i] = xr[i] * inv * w[i];
}

// ---------------- tf32 helpers ----------------
__device__ __forceinline__ float cvt_tf32(float x) {
    unsigned u; asm("cvt.rna.tf32.f32 %0, %1;" : "=r"(u) : "f"(x));
    return __uint_as_float(u);
}
__device__ __forceinline__ void mma8(float* d, float a0, float a1, float a2, float a3,
                                     float b0, float b1) {
    unsigned A0=__float_as_uint(a0), A1=__float_as_uint(a1);
    unsigned A2=__float_as_uint(a2), A3=__float_as_uint(a3);
    unsigned B0=__float_as_uint(b0), B1=__float_as_uint(b1);
    asm volatile("mma.sync.aligned.m16n8k8.row.col.f32.tf32.tf32.f32 "
                 "{%0,%1,%2,%3},{%4,%5,%6,%7},{%8,%9},{%0,%1,%2,%3};"
                 : "+f"(d[0]), "+f"(d[1]), "+f"(d[2]), "+f"(d[3])
                 : "r"(A0), "r"(A1), "r"(A2), "r"(A3), "r"(B0), "r"(B1));
}

// ---------------- tensor-core GEMM (NT): C[M,N] = A[M,K] x B[N,K]^T ------
// P = 1 (tf32 single pass) or 3 (tf32 hi/lo split, ~fp32 precision)
// MODE: 0 plain, 1 +residual R, 2 expert1 (gather rows, SiLU -> g_he),
//       3 expert2 (A = g_he rows, scaled scatter -> g_ybuf)
#define LDK 136
#define MATF (32*LDK)
template<int P, int MODE>
__global__ void __launch_bounds__(256, 1) gemm_tc(const float* __restrict__ A,
                                                  const float* __restrict__ B,
                                                  float* __restrict__ C,
                                                  const float* __restrict__ R,
                                                  int K, int lda, int ldb, int ldc) {
    extern __shared__ float smf[];
    const int NMAT = (P == 3) ? 4 : 2;
    const int bm = blockIdx.y << 7, bn = blockIdx.x << 7;
    int off = 0, cnt = 0x7fffffff;
    const float* Bp = B;
    if (MODE >= 2) {
        int e = blockIdx.z;
        cnt = g_cnt[e];
        if (cnt == 0 || bm >= cnt) return;
        off = g_off[e];
        Bp = B + (size_t)e * 1024 * 1024;
    }
    const int tid = threadIdx.x;
    const int lane = tid & 31, w = tid >> 5;
    const int g2 = lane >> 2, t4 = lane & 3;
    const int wm = (w >> 2) << 6, wn = (w & 3) << 5;
    const int r = tid & 127, ks = (tid >> 7) << 4;

    const float* Arow;
    if (MODE == 2) {
        int gr = bm + r; if (gr >= cnt) gr = cnt - 1;
        Arow = A + (size_t)g_ptok[off + gr] * lda + ks;
    } else if (MODE == 3) {
        int gr = bm + r; if (gr >= cnt) gr = cnt - 1;
        Arow = A + (size_t)(off + gr) * lda + ks;
    } else {
        Arow = A + (size_t)(bm + r) * lda + ks;
    }
    const float* Brow = Bp + (size_t)(bn + r) * ldb + ks;

    float acc[4][4][4];
#pragma unroll
    for (int i = 0; i < 4; i++)
#pragma unroll
        for (int j = 0; j < 4; j++)
#pragma unroll
            for (int q = 0; q < 4; q++) acc[i][j][q] = 0.f;

    float4 ra[4], rb[4];

    auto ldg = [&](int k0) {
#pragma unroll
        for (int c = 0; c < 4; c++) {
            ra[c] = *(const float4*)(Arow + k0 + 4*c);
            rb[c] = *(const float4*)(Brow + k0 + 4*c);
        }
    };
    auto sts = [&](int buf) {
        float* S  = smf + buf * NMAT * MATF;
        float* Ah = S;
        float* Bh = S + MATF;
        float* Al = S + 2*MATF;
        float* Bl = S + 3*MATF;
#pragma unroll
        for (int c = 0; c < 4; c++) {
            int kl = ks + 4*c;
            float av[4] = {ra[c].x, ra[c].y, ra[c].z, ra[c].w};
            float bv[4] = {rb[c].x, rb[c].y, rb[c].z, rb[c].w};
#pragma unroll
            for (int j = 0; j < 4; j++) {
                float ah = cvt_tf32(av[j]);
                float bh = cvt_tf32(bv[j]);
                Ah[(kl+j)*LDK + r] = ah;
                Bh[(kl+j)*LDK + r] = bh;
                if (P == 3) {
                    Al[(kl+j)*LDK + r] = cvt_tf32(av[j] - ah);
                    Bl[(kl+j)*LDK + r] = cvt_tf32(bv[j] - bh);
                }
            }
        }
    };
    auto compute = [&](int buf) {
        const float* S  = smf + buf * NMAT * MATF;
        const float* Ah = S;
        const float* Bh = S + MATF;
        const float* Al = S + 2*MATF;
        const float* Bl = S + 3*MATF;
#pragma unroll
        for (int kb = 0; kb < 4; kb++) {
            int rowL = (kb*8 + t4) * LDK;
            int rowH = rowL + 4*LDK;
            float ah[4][4], bh[4][2], al[4][4], bl[4][2];
#pragma unroll
            for (int i = 0; i < 4; i++) {
                int m = wm + 16*i + g2;
                ah[i][0]=Ah[rowL+m]; ah[i][1]=Ah[rowL+m+8];
                ah[i][2]=Ah[rowH+m]; ah[i][3]=Ah[rowH+m+8];
                if (P == 3) {
                    al[i][0]=Al[rowL+m]; al[i][1]=Al[rowL+m+8];
                    al[i][2]=Al[rowH+m]; al[i][3]=Al[rowH+m+8];
                }
            }
#pragma unroll
            for (int j = 0; j < 4; j++) {
                int n = wn + 8*j + g2;
                bh[j][0]=Bh[rowL+n]; bh[j][1]=Bh[rowH+n];
                if (P == 3) { bl[j][0]=Bl[rowL+n]; bl[j][1]=Bl[rowH+n]; }
            }
#pragma unroll
            for (int i = 0; i < 4; i++)
#pragma unroll
                for (int j = 0; j < 4; j++) {
                    mma8(acc[i][j], ah[i][0],ah[i][1],ah[i][2],ah[i][3], bh[j][0],bh[j][1]);
                    if (P == 3) {
                        mma8(acc[i][j], ah[i][0],ah[i][1],ah[i][2],ah[i][3], bl[j][0],bl[j][1]);
                        mma8(acc[i][j], al[i][0],al[i][1],al[i][2],al[i][3], bh[j][0],bh[j][1]);
                    }
                }
        }
    };

    ldg(0); sts(0); __syncthreads();
    const int NS = K >> 5;
    for (int ko = 0; ko < NS; ko++) {
        if (ko + 1 < NS) ldg((ko + 1) << 5);
        compute(ko & 1);
        if (ko + 1 < NS) { sts((ko + 1) & 1); __syncthreads(); }
    }

    // epilogue
#pragma unroll
    for (int i = 0; i < 4; i++) {
#pragma unroll
        for (int j = 0; j < 4; j++) {
            int m0 = bm + wm + 16*i + g2, m1 = m0 + 8;
            int nc = bn + wn + 8*j + 2*t4;
            float2 v0 = make_float2(acc[i][j][0], acc[i][j][1]);
            float2 v1 = make_float2(acc[i][j][2], acc[i][j][3]);
            if (MODE == 0 || MODE == 1) {
                size_t o0 = (size_t)m0 * ldc + nc, o1 = (size_t)m1 * ldc + nc;
                if (MODE == 1) {
                    float2 r0 = *(const float2*)(R + o0);
                    float2 r1 = *(const float2*)(R + o1);
                    v0.x += r0.x; v0.y += r0.y; v1.x += r1.x; v1.y += r1.y;
                }
                *(float2*)(C + o0) = v0;
                *(float2*)(C + o1) = v1;
            } else if (MODE == 2) {
                if (m0 < cnt) {
                    float2 s = make_float2(v0.x/(1.f+expf(-v0.x)), v0.y/(1.f+expf(-v0.y)));
                    *(float2*)(g_he + (size_t)(off+m0)*1024 + nc) = s;
                }
                if (m1 < cnt) {
                    float2 s = make_float2(v1.x/(1.f+expf(-v1.x)), v1.y/(1.f+expf(-v1.y)));
                    *(float2*)(g_he + (size_t)(off+m1)*1024 + nc) = s;
                }
            } else {
                if (m0 < cnt) {
                    int p = off + m0; float sc = g_pscale[p]; int d = g_pdst[p];
                    *(float2*)(g_ybuf + (size_t)d*1024 + nc) = make_float2(v0.x*sc, v0.y*sc);
                }
                if (m1 < cnt) {
                    int p = off + m1; float sc = g_pscale[p]; int d = g_pdst[p];
                    *(float2*)(g_ybuf + (size_t)d*1024 + nc) = make_float2(v1.x*sc, v1.y*sc);
                }
            }
        }
    }
}

// ---------------- flash attention (causal, d=128, fp32) -------------------
#define ATTN_SMEM_FLOATS 22016
__global__ void __launch_bounds__(256) attn_kernel(const float* __restrict__ q,
                                                   const float* __restrict__ kv,
                                                   float* __restrict__ o) {
    extern __shared__ float sm[];
    float* Qt   = sm;
    float* KV   = sm + 8192;
    float* Ps   = sm + 8192 + 8448;
    float* red  = Ps + 64 * 65;
    float* mrow = red + 1024;
    float* lrow = mrow + 64;
    float* rsb  = lrow + 64;

    const int qt = blockIdx.x, head = blockIdx.y, b = blockIdx.z;
    const int tid = threadIdx.x, tx = tid & 15, ty = tid >> 4;
    const int qbase = qt << 6;
    const size_t tok0 = (size_t)b * SEQ;
    const int hoff = head << 7;

#pragma unroll
    for (int it = 0; it < 8; it++) {
        int lin = tid + (it << 8);
        int r = lin >> 5, d0 = (lin & 31) << 2;
        float4 v = *(const float4*)(q + (tok0 + qbase + r) * 1024 + hoff + d0);
        Qt[(d0+0)*64 + r] = v.x; Qt[(d0+1)*64 + r] = v.y;
        Qt[(d0+2)*64 + r] = v.z; Qt[(d0+3)*64 + r] = v.w;
    }
    if (tid < 64) { mrow[tid] = -1e30f; lrow[tid] = 0.f; }

    float acc[4][8];
#pragma unroll
    for (int i = 0; i < 4; i++)
#pragma unroll
        for (int j = 0; j < 8; j++) acc[i][j] = 0.f;

    for (int kt = 0; kt <= qt; kt++) {
        __syncthreads();
#pragma unroll
        for (int it = 0; it < 8; it++) {
            int lin = tid + (it << 8);
            int c = lin >> 5, d0 = (lin & 31) << 2;
            float4 v = *(const float4*)(kv + (tok0 + (kt<<6) + c) * 2048 + hoff + d0);
            float* dst = KV + c * 129 + d0;
            dst[0]=v.x; dst[1]=v.y; dst[2]=v.z; dst[3]=v.w;
        }
        __syncthreads();
        float s[4][4] = {};
        const float* qb = Qt + (ty << 2);
        const float* kb = KV + (tx << 2) * 129;
#pragma unroll 4
        for (int d = 0; d < 128; d++) {
            float4 av = *(const float4*)(qb + d * 64);
            float b0 = kb[d], b1 = kb[129 + d], b2 = kb[258 + d], b3 = kb[387 + d];
            s[0][0]+=av.x*b0; s[0][1]+=av.x*b1; s[0][2]+=av.x*b2; s[0][3]+=av.x*b3;
            s[1][0]+=av.y*b0; s[1][1]+=av.y*b1; s[1][2]+=av.y*b2; s[1][3]+=av.y*b3;
            s[2][0]+=av.z*b0; s[2][1]+=av.z*b1; s[2][2]+=av.z*b2; s[2][3]+=av.z*b3;
            s[3][0]+=av.w*b0; s[3][1]+=av.w*b1; s[3][2]+=av.w*b2; s[3][3]+=av.w*b3;
        }
#pragma unroll
        for (int i = 0; i < 4; i++)
#pragma unroll
            for (int j = 0; j < 4; j++) s[i][j] *= SCALE_F;
        if (kt == qt) {
#pragma unroll
            for (int i = 0; i < 4; i++)
#pragma unroll
                for (int j = 0; j < 4; j++)
                    if ((kt<<6) + (tx<<2) + j > qbase + (ty<<2) + i) s[i][j] = -1e30f;
        }
#pragma unroll
        for (int i = 0; i < 4; i++) {
            float mx = fmaxf(fmaxf(s[i][0], s[i][1]), fmaxf(s[i][2], s[i][3]));
            red[((ty<<2)+i)*16 + tx] = mx;
        }
        __syncthreads();
#pragma unroll
        for (int it = 0; it < 8; it++) {
            int lin = tid + (it << 8);
            int c = lin >> 5, d0 = (lin & 31) << 2;
            float4 v = *(const float4*)(kv + (tok0 + (kt<<6) + c) * 2048 + 1024 + hoff + d0);
            float* dst = KV + c * 132 + d0;
            dst[0]=v.x; dst[1]=v.y; dst[2]=v.z; dst[3]=v.w;
        }
        if (tid < 64) {
            float mx = mrow[tid];
#pragma unroll
            for (int k = 0; k < 16; k++) mx = fmaxf(mx, red[tid*16 + k]);
            rsb[tid]  = expf(mrow[tid] - mx);
            mrow[tid] = mx;
        }
        __syncthreads();
#pragma unroll
        for (int i = 0; i < 4; i++) {
            int r = (ty << 2) + i;
            float m = mrow[r], f = rsb[r];
            float p0 = expf(s[i][0]-m), p1 = expf(s[i][1]-m);
            float p2 = expf(s[i][2]-m), p3 = expf(s[i][3]-m);
            Ps[((tx<<2)+0)*65 + r] = p0; Ps[((tx<<2)+1)*65 + r] = p1;
            Ps[((tx<<2)+2)*65 + r] = p2; Ps[((tx<<2)+3)*65 + r] = p3;
            red[r*16 + tx] = p0 + p1 + p2 + p3;
#pragma unroll
            for (int j = 0; j < 8; j++) acc[i][j] *= f;
        }
        __syncthreads();
        if (tid < 64) {
            float sum = 0.f;
#pragma unroll
            for (int k = 0; k < 16; k++) sum += red[tid*16 + k];
            lrow[tid] = lrow[tid] * rsb[tid] + sum;
        }
        const float* pb = Ps + (ty << 2);
        const float* vb = KV + (tx << 3);
#pragma unroll 2
        for (int kk = 0; kk < 64; kk++) {
            float4 v0 = *(const float4*)(vb + kk*132);
            float4 v1 = *(const float4*)(vb + kk*132 + 4);
            float p0 = pb[kk*65+0], p1 = pb[kk*65+1], p2 = pb[kk*65+2], p3 = pb[kk*65+3];
            acc[0][0]+=p0*v0.x; acc[0][1]+=p0*v0.y; acc[0][2]+=p0*v0.z; acc[0][3]+=p0*v0.w;
            acc[0][4]+=p0*v1.x; acc[0][5]+=p0*v1.y; acc[0][6]+=p0*v1.z; acc[0][7]+=p0*v1.w;
            acc[1][0]+=p1*v0.x; acc[1][1]+=p1*v0.y; acc[1][2]+=p1*v0.z; acc[1][3]+=p1*v0.w;
            acc[1][4]+=p1*v1.x; acc[1][5]+=p1*v1.y; acc[1][6]+=p1*v1.z; acc[1][7]+=p1*v1.w;
            acc[2][0]+=p2*v0.x; acc[2][1]+=p2*v0.y; acc[2][2]+=p2*v0.z; acc[2][3]+=p2*v0.w;
            acc[2][4]+=p2*v1.x; acc[2][5]+=p2*v1.y; acc[2][6]+=p2*v1.z; acc[2][7]+=p2*v1.w;
            acc[3][0]+=p3*v0.x; acc[3][1]+=p3*v0.y; acc[3][2]+=p3*v0.z; acc[3][3]+=p3*v0.w;
            acc[3][4]+=p3*v1.x; acc[3][5]+=p3*v1.y; acc[3][6]+=p3*v1.z; acc[3][7]+=p3*v1.w;
        }
    }
    __syncthreads();
#pragma unroll
    for (int i = 0; i < 4; i++) {
        int r = (ty << 2) + i;
        float inv = 1.f / lrow[r];
        float* op = o + (tok0 + qbase + r) * 1024 + hoff + (tx << 3);
        *(float4*)op     = make_float4(acc[i][0]*inv, acc[i][1]*inv, acc[i][2]*inv, acc[i][3]*inv);
        *(float4*)(op+4) = make_float4(acc[i][4]*inv, acc[i][5]*inv, acc[i][6]*inv, acc[i][7]*inv);
    }
}

// ---------------- MoE gate ---------------
__global__ void gate_kernel(const float* __restrict__ h2, const float* __restrict__ gw) {
    int t = blockIdx.x;
    int w = threadIdx.x >> 5, lane = threadIdx.x & 31;
    const float* xr = h2 + (size_t)t * HD;
    const float* gr = gw + (size_t)w * HD;
    float ss = 0.f;
    for (int i = lane; i < HD; i += 32) ss += xr[i] * gr[i];
#pragma unroll
    for (int o = 16; o > 0; o >>= 1) ss += __shfl_down_sync(0xffffffffu, ss, o);
    __shared__ float lg[NEXP];
    if (lane == 0) lg[w] = ss;
    __syncthreads();
    if (threadIdx.x == 0) {
        int i1 = 0;
#pragma unroll
        for (int e = 1; e < NEXP; e++) if (lg[e] > lg[i1]) i1 = e;
        int i2 = (i1 == 0) ? 1 : 0;
#pragma unroll
        for (int e = 0; e < NEXP; e++) if (e != i1 && lg[e] > lg[i2]) i2 = e;
        float e2 = expf(lg[i2] - lg[i1]);
        float inv = 1.f / (1.f + e2);
        g_topi[2*t]   = i1; g_topw[2*t]   = inv;
        g_topi[2*t+1] = i2; g_topw[2*t+1] = e2 * inv;
    }
}

// ---------------- deterministic expert grouping --------------------------
__global__ void route_group_kernel() {
    __shared__ int hist[NEXP * 256];
    __shared__ int soff[NEXP + 1];
    __shared__ int stot[NEXP];
    int tid = threadIdx.x;
    int t0 = tid * 8;
    int lc[NEXP];
#pragma unroll
    for (int e = 0; e < NEXP; e++) lc[e] = 0;
    for (int t = t0; t < t0 + 8; t++) {
        lc[g_topi[2*t]]++; lc[g_topi[2*t+1]]++;
    }
#pragma unroll
    for (int e = 0; e < NEXP; e++) hist[e * 256 + tid] = lc[e];
    __syncthreads();
    if (tid < NEXP) {
        int a = 0;
        for (int i = 0; i < 256; i++) { int v = hist[tid*256+i]; hist[tid*256+i] = a; a += v; }
        stot[tid] = a;
    }
    __syncthreads();
    if (tid == 0) {
        int a = 0;
        for (int e = 0; e < NEXP; e++) { soff[e] = a; g_off[e] = a; g_cnt[e] = stot[e]; a += stot[e]; }
        soff[NEXP] = a;
    }
    __syncthreads();
    int pos[NEXP];
#pragma unroll
    for (int e = 0; e < NEXP; e++) pos[e] = soff[e] + hist[e * 256 + tid];
    for (int t = t0; t < t0 + 8; t++) {
        for (int s2 = 0; s2 < 2; s2++) {
            int e = g_topi[2*t + s2];
            int p = pos[e]++;
            g_ptok[p] = t; g_pdst[p] = 2*t + s2; g_pscale[p] = g_topw[2*t + s2];
        }
    }
}

// ---------------- elementwise tails --------------------------------------
__global__ void swiglu_kernel(const float* __restrict__ gu, float* __restrict__ act) {
    int t = blockIdx.x, i = threadIdx.x;
    float4 g = *(const float4*)(gu + (size_t)t*2048 + 4*i);
    float4 u = *(const float4*)(gu + (size_t)t*2048 + 1024 + 4*i);
    float4 r;
    r.x = g.x / (1.f + expf(-g.x)) * u.x;
    r.y = g.y / (1.f + expf(-g.y)) * u.y;
    r.z = g.z / (1.f + expf(-g.z)) * u.z;
    r.w = g.w / (1.f + expf(-g.w)) * u.w;
    *(float4*)(act + (size_t)t*HD + 4*i) = r;
}

__global__ void add_routed_kernel(float* __restrict__ out) {
    int t = blockIdx.x, i = threadIdx.x;
    float4 a = *(const float4*)(out + (size_t)t*HD + 4*i);
    float4 y0 = *(const float4*)(g_ybuf + (size_t)(2*t)*HD + 4*i);
    float4 y1 = *(const float4*)(g_ybuf + (size_t)(2*t+1)*HD + 4*i);
    a.x += y0.x + y1.x; a.y += y0.y + y1.y; a.z += y0.z + y1.z; a.w += y0.w + y1.w;
    *(float4*)(out + (size_t)t*HD + 4*i) = a;
}

// ---------------- launch ---------------------------------------------------
extern "C" void kernel_launch(void* const* d_in, const int* in_sizes, int n_in,
                              void* d_out, int out_size) {
    const float* x    = (const float*)d_in[0];
    const float* ln1  = (const float*)d_in[2];
    const float* ln2  = (const float*)d_in[3];
    const float* Wq   = (const float*)d_in[4];
    const float* Wkv  = (const float*)d_in[5];
    const float* Wo   = (const float*)d_in[6];
    const float* gate = (const float*)d_in[7];
    const float* w1   = (const float*)d_in[8];
    const float* w2   = (const float*)d_in[9];
    const float* sgu  = (const float*)d_in[10];
    const float* sdwn = (const float*)d_in[11];
    float* out = (float*)d_out;

    float *p_wqp, *p_h, *p_q, *p_kv, *p_attn, *p_x2, *p_h2, *p_gu, *p_act, *p_he;
    cudaGetSymbolAddress((void**)&p_wqp,  g_wqp);
    cudaGetSymbolAddress((void**)&p_h,    g_h);
    cudaGetSymbolAddress((void**)&p_q,    g_q);
    cudaGetSymbolAddress((void**)&p_kv,   g_kv);
    cudaGetSymbolAddress((void**)&p_attn, g_attn);
    cudaGetSymbolAddress((void**)&p_x2,   g_x2);
    cudaGetSymbolAddress((void**)&p_h2,   g_h2);
    cudaGetSymbolAddress((void**)&p_gu,   g_gu);
    cudaGetSymbolAddress((void**)&p_act,  g_act);
    cudaGetSymbolAddress((void**)&p_he,   g_he);

    const int ATTN_SMEM = ATTN_SMEM_FLOATS * 4;
    cudaFuncSetAttribute(attn_kernel, cudaFuncAttributeMaxDynamicSharedMemorySize, ATTN_SMEM);
    const int SM_P1 = 2 * 2 * MATF * 4;   // 69632 B
    const int SM_P3 = 2 * 4 * MATF * 4;   // 139264 B
    cudaFuncSetAttribute(gemm_tc<3,0>, cudaFuncAttributeMaxDynamicSharedMemorySize, SM_P3);
    cudaFuncSetAttribute(gemm_tc<3,1>, cudaFuncAttributeMaxDynamicSharedMemorySize, SM_P3);
    cudaFuncSetAttribute(gemm_tc<1,0>, cudaFuncAttributeMaxDynamicSharedMemorySize, SM_P1);
    cudaFuncSetAttribute(gemm_tc<1,1>, cudaFuncAttributeMaxDynamicSharedMemorySize, SM_P1);
    cudaFuncSetAttribute(gemm_tc<1,2>, cudaFuncAttributeMaxDynamicSharedMemorySize, SM_P1);
    cudaFuncSetAttribute(gemm_tc<1,3>, cudaFuncAttributeMaxDynamicSharedMemorySize, SM_P1);

    // attention block (routing-critical: tf32 3-pass = ~fp32 precision)
    pack_wq_kernel<<<1024, 256>>>(Wq, p_wqp);
    rmsnorm_kernel<<<TT, 256>>>(x, ln1, p_h);
    gemm_tc<3,0><<<dim3(8, 16), 256, SM_P3>>>(p_h, p_wqp, p_q,  nullptr, 1024, 1024, 1024, 1024);
    gemm_tc<3,0><<<dim3(16,16), 256, SM_P3>>>(p_h, Wkv,   p_kv, nullptr, 1024, 1024, 1024, 2048);
    attn_kernel<<<dim3(16, NH, 2), 256, ATTN_SMEM>>>(p_q, p_kv, p_attn);
    gemm_tc<3,1><<<dim3(8, 16), 256, SM_P3>>>(p_attn, Wo, p_x2, x, 1024, 1024, 1024, 1024);

    // MoE block
    rmsnorm_kernel<<<TT, 256>>>(p_x2, ln2, p_h2);
    gate_kernel<<<TT, 256>>>(p_h2, gate);
    route_group_kernel<<<1, 256>>>();
    gemm_tc<1,2><<<dim3(8, 16, NEXP), 256, SM_P1>>>(p_h2, w1, nullptr, nullptr, 1024, 1024, 1024, 1024);
    gemm_tc<1,3><<<dim3(8, 16, NEXP), 256, SM_P1>>>(p_he, w2, nullptr, nullptr, 1024, 1024, 1024, 1024);

    // shared expert
    gemm_tc<1,0><<<dim3(16,16), 256, SM_P1>>>(p_h2, sgu, p_gu, nullptr, 1024, 1024, 1024, 2048);
    swiglu_kernel<<<TT, 256>>>(p_gu, p_act);
    gemm_tc<1,1><<<dim3(8, 16), 256, SM_P1>>>(p_act, sdwn, out, p_x2, 1024, 1024, 1024, 1024);

    // combine routed experts
    add_routed_kernel<<<TT, 256>>>(out);
}

// round 3
// speedup vs baseline: 1.6368x; 1.2044x over previous
#include <cuda_runtime.h>
#include <math.h>

#define TT    2048      // tokens = B*S
#define HD    1024      // hidden
#define NH    8
#define SEQ   1024
#define NEXP  8
#define SCALE_F 0.07216878364870322f   // 192^-0.5

// ---------------- scratch (no runtime allocation allowed) ----------------
__device__ float g_wqp [1024*1024];
__device__ float g_h   [TT*HD];
__device__ float g_q   [TT*1024];
__device__ float g_kv  [TT*2048];
__device__ float g_attn[TT*1024];
__device__ float g_x2  [TT*HD];
__device__ float g_h2  [TT*HD];
__device__ float g_gu  [TT*2048];
__device__ float g_act [TT*1024];
__device__ float g_he  [2*TT*1024];
__device__ float g_ybuf[2*TT*1024];
__device__ float g_topw[2*TT];
__device__ float g_pscale[2*TT];
__device__ int   g_topi[2*TT];
__device__ int   g_ptok[2*TT];
__device__ int   g_pdst[2*TT];
__device__ int   g_cnt [NEXP];
__device__ int   g_off [NEXP];

// ---------------- pack Wq: keep only nope dims ----------
__global__ void pack_wq_kernel(const float* __restrict__ Wq, float* __restrict__ Wqp) {
    int r = blockIdx.x;
    int h = r >> 7, d = r & 127;
    const float4* src = (const float4*)(Wq + (size_t)(h*192 + d) * HD);
    float4*       dst = (float4*)(Wqp + (size_t)r * HD);
    dst[threadIdx.x] = src[threadIdx.x];
}

// ---------------- rmsnorm ----------------
__global__ void rmsnorm_kernel(const float* __restrict__ x, const float* __restrict__ w,
                               float* __restrict__ out) {
    int t = blockIdx.x;
    const float* xr = x + (size_t)t * HD;
    float ss = 0.f;
    for (int i = threadIdx.x; i < HD; i += 256) { float v = xr[i]; ss += v * v; }
    __shared__ float red[256];
    red[threadIdx.x] = ss; __syncthreads();
    for (int o = 128; o > 0; o >>= 1) {
        if (threadIdx.x < o) red[threadIdx.x] += red[threadIdx.x + o];
        __syncthreads();
    }
    float inv = rsqrtf(red[0] * (1.f / HD) + 1e-6f);
    for (int i = threadIdx.x; i < HD; i += 256)
        out[(size_t)t * HD + i] = xr[i] * inv * w[i];
}

// ---------------- tf32 helpers ----------------
__device__ __forceinline__ float cvt_tf32(float x) {
    unsigned u; asm("cvt.rna.tf32.f32 %0, %1;" : "=r"(u) : "f"(x));
    return __uint_as_float(u);
}
__device__ __forceinline__ void mma8(float* d, float a0, float a1, float a2, float a3,
                                     float b0, float b1) {
    unsigned A0=__float_as_uint(a0), A1=__float_as_uint(a1);
    unsigned A2=__float_as_uint(a2), A3=__float_as_uint(a3);
    unsigned B0=__float_as_uint(b0), B1=__float_as_uint(b1);
    asm volatile("mma.sync.aligned.m16n8k8.row.col.f32.tf32.tf32.f32 "
                 "{%0,%1,%2,%3},{%4,%5,%6,%7},{%8,%9},{%0,%1,%2,%3};"
                 : "+f"(d[0]), "+f"(d[1]), "+f"(d[2]), "+f"(d[3])
                 : "r"(A0), "r"(A1), "r"(A2), "r"(A3), "r"(B0), "r"(B1));
}

// ---------------- tensor-core GEMM (NT): C[M,N] = A[M,K] x B[N,K]^T ------
#define LDK 136
#define MATF (32*LDK)
template<int P, int MODE>
__global__ void __launch_bounds__(256, 1) gemm_tc(const float* __restrict__ A,
                                                  const float* __restrict__ B,
                                                  float* __restrict__ C,
                                                  const float* __restrict__ R,
                                                  int K, int lda, int ldb, int ldc) {
    extern __shared__ float smf[];
    const int NMAT = (P == 3) ? 4 : 2;
    const int bm = blockIdx.y << 7, bn = blockIdx.x << 7;
    int off = 0, cnt = 0x7fffffff;
    const float* Bp = B;
    if (MODE >= 2) {
        int e = blockIdx.z;
        cnt = g_cnt[e];
        if (cnt == 0 || bm >= cnt) return;
        off = g_off[e];
        Bp = B + (size_t)e * 1024 * 1024;
    }
    const int tid = threadIdx.x;
    const int lane = tid & 31, w = tid >> 5;
    const int g2 = lane >> 2, t4 = lane & 3;
    const int wm = (w >> 2) << 6, wn = (w & 3) << 5;
    const int r = tid & 127, ks = (tid >> 7) << 4;

    const float* Arow;
    if (MODE == 2) {
        int gr = bm + r; if (gr >= cnt) gr = cnt - 1;
        Arow = A + (size_t)g_ptok[off + gr] * lda + ks;
    } else if (MODE == 3) {
        int gr = bm + r; if (gr >= cnt) gr = cnt - 1;
        Arow = A + (size_t)(off + gr) * lda + ks;
    } else {
        Arow = A + (size_t)(bm + r) * lda + ks;
    }
    const float* Brow = Bp + (size_t)(bn + r) * ldb + ks;

    float acc[4][4][4];
#pragma unroll
    for (int i = 0; i < 4; i++)
#pragma unroll
        for (int j = 0; j < 4; j++)
#pragma unroll
            for (int q = 0; q < 4; q++) acc[i][j][q] = 0.f;

    float4 ra[4], rb[4];

    auto ldg = [&](int k0) {
#pragma unroll
        for (int c = 0; c < 4; c++) {
            ra[c] = *(const float4*)(Arow + k0 + 4*c);
            rb[c] = *(const float4*)(Brow + k0 + 4*c);
        }
    };
    auto sts = [&](int buf) {
        float* S  = smf + buf * NMAT * MATF;
        float* Ah = S;
        float* Bh = S + MATF;
        float* Al = S + 2*MATF;
        float* Bl = S + 3*MATF;
#pragma unroll
        for (int c = 0; c < 4; c++) {
            int kl = ks + 4*c;
            float av[4] = {ra[c].x, ra[c].y, ra[c].z, ra[c].w};
            float bv[4] = {rb[c].x, rb[c].y, rb[c].z, rb[c].w};
#pragma unroll
            for (int j = 0; j < 4; j++) {
                float ah = cvt_tf32(av[j]);
                float bh = cvt_tf32(bv[j]);
                Ah[(kl+j)*LDK + r] = ah;
                Bh[(kl+j)*LDK + r] = bh;
                if (P == 3) {
                    Al[(kl+j)*LDK + r] = cvt_tf32(av[j] - ah);
                    Bl[(kl+j)*LDK + r] = cvt_tf32(bv[j] - bh);
                }
            }
        }
    };
    auto compute = [&](int buf) {
        const float* S  = smf + buf * NMAT * MATF;
        const float* Ah = S;
        const float* Bh = S + MATF;
        const float* Al = S + 2*MATF;
        const float* Bl = S + 3*MATF;
#pragma unroll
        for (int kb = 0; kb < 4; kb++) {
            int rowL = (kb*8 + t4) * LDK;
            int rowH = rowL + 4*LDK;
            float ah[4][4], bh[4][2], al[4][4], bl[4][2];
#pragma unroll
            for (int i = 0; i < 4; i++) {
                int m = wm + 16*i + g2;
                ah[i][0]=Ah[rowL+m]; ah[i][1]=Ah[rowL+m+8];
                ah[i][2]=Ah[rowH+m]; ah[i][3]=Ah[rowH+m+8];
                if (P == 3) {
                    al[i][0]=Al[rowL+m]; al[i][1]=Al[rowL+m+8];
                    al[i][2]=Al[rowH+m]; al[i][3]=Al[rowH+m+8];
                }
            }
#pragma unroll
            for (int j = 0; j < 4; j++) {
                int n = wn + 8*j + g2;
                bh[j][0]=Bh[rowL+n]; bh[j][1]=Bh[rowH+n];
                if (P == 3) { bl[j][0]=Bl[rowL+n]; bl[j][1]=Bl[rowH+n]; }
            }
#pragma unroll
            for (int i = 0; i < 4; i++)
#pragma unroll
                for (int j = 0; j < 4; j++) {
                    mma8(acc[i][j], ah[i][0],ah[i][1],ah[i][2],ah[i][3], bh[j][0],bh[j][1]);
                    if (P == 3) {
                        mma8(acc[i][j], ah[i][0],ah[i][1],ah[i][2],ah[i][3], bl[j][0],bl[j][1]);
                        mma8(acc[i][j], al[i][0],al[i][1],al[i][2],al[i][3], bh[j][0],bh[j][1]);
                    }
                }
        }
    };

    ldg(0); sts(0); __syncthreads();
    const int NS = K >> 5;
    for (int ko = 0; ko < NS; ko++) {
        if (ko + 1 < NS) ldg((ko + 1) << 5);
        compute(ko & 1);
        if (ko + 1 < NS) { sts((ko + 1) & 1); __syncthreads(); }
    }

    // epilogue
#pragma unroll
    for (int i = 0; i < 4; i++) {
#pragma unroll
        for (int j = 0; j < 4; j++) {
            int m0 = bm + wm + 16*i + g2, m1 = m0 + 8;
            int nc = bn + wn + 8*j + 2*t4;
            float2 v0 = make_float2(acc[i][j][0], acc[i][j][1]);
            float2 v1 = make_float2(acc[i][j][2], acc[i][j][3]);
            if (MODE == 0 || MODE == 1) {
                size_t o0 = (size_t)m0 * ldc + nc, o1 = (size_t)m1 * ldc + nc;
                if (MODE == 1) {
                    float2 r0 = *(const float2*)(R + o0);
                    float2 r1 = *(const float2*)(R + o1);
                    v0.x += r0.x; v0.y += r0.y; v1.x += r1.x; v1.y += r1.y;
                }
                *(float2*)(C + o0) = v0;
                *(float2*)(C + o1) = v1;
            } else if (MODE == 2) {
                if (m0 < cnt) {
                    float2 s = make_float2(v0.x/(1.f+expf(-v0.x)), v0.y/(1.f+expf(-v0.y)));
                    *(float2*)(g_he + (size_t)(off+m0)*1024 + nc) = s;
                }
                if (m1 < cnt) {
                    float2 s = make_float2(v1.x/(1.f+expf(-v1.x)), v1.y/(1.f+expf(-v1.y)));
                    *(float2*)(g_he + (size_t)(off+m1)*1024 + nc) = s;
                }
            } else {
                if (m0 < cnt) {
                    int p = off + m0; float sc = g_pscale[p]; int d = g_pdst[p];
                    *(float2*)(g_ybuf + (size_t)d*1024 + nc) = make_float2(v0.x*sc, v0.y*sc);
                }
                if (m1 < cnt) {
                    int p = off + m1; float sc = g_pscale[p]; int d = g_pdst[p];
                    *(float2*)(g_ybuf + (size_t)d*1024 + nc) = make_float2(v1.x*sc, v1.y*sc);
                }
            }
        }
    }
}

// ---------------- flash attention v2: tensor-core tf32 --------------------
// QK^T: 3-pass tf32 (routing-critical precision); PV: 1-pass tf32.
// 256 threads, tile 64 q-rows x 64 kv-cols, d=128.
#define A_LDQ 132
#define A_LDV 136
#define A_LDP 68
// floats: Qh,Ql,Kh,Kl: 4*64*132; Vt: 64*136; Ps: 64*68; red/red2: 128+128; m/l: 64+64
#define ATTN2_FLOATS (4*64*A_LDQ + 64*A_LDV + 64*A_LDP + 128 + 128 + 64 + 64)
__global__ void __launch_bounds__(256, 1) attn_tc_kernel(const float* __restrict__ q,
                                                         const float* __restrict__ kv,
                                                         float* __restrict__ o) {
    extern __shared__ float sm[];
    float* Qh   = sm;
    float* Ql   = Qh + 64*A_LDQ;
    float* Kh   = Ql + 64*A_LDQ;
    float* Kl   = Kh + 64*A_LDQ;
    float* Vt   = Kl + 64*A_LDQ;
    float* Ps   = Vt + 64*A_LDV;
    float* red  = Ps + 64*A_LDP;
    float* red2 = red + 128;
    float* mrow = red2 + 128;
    float* lrow = mrow + 64;

    const int qt = 15 - blockIdx.x;         // heavy blocks first
    const int head = blockIdx.y, b = blockIdx.z;
    const int tid = threadIdx.x, lane = tid & 31, wid = tid >> 5;
    const int g2 = lane >> 2, t4 = lane & 3;
    const int wm = (wid & 3) << 4;          // warp m offset: 0,16,32,48
    const int wn = wid >> 2;                // warp n half: 0 or 1
    const int qbase = qt << 6;
    const size_t tok0 = (size_t)b * SEQ;
    const int hoff = head << 7;

    // stage Q (hi/lo) once
#pragma unroll
    for (int it = 0; it < 8; it++) {
        int lin = tid + (it << 8);
        int r = lin >> 5, c4 = (lin & 31) << 2;
        float4 v = *(const float4*)(q + (tok0 + qbase + r) * 1024 + hoff + c4);
        float h0 = cvt_tf32(v.x), h1 = cvt_tf32(v.y), h2 = cvt_tf32(v.z), h3 = cvt_tf32(v.w);
        *(float4*)(Qh + r*A_LDQ + c4) = make_float4(h0, h1, h2, h3);
        *(float4*)(Ql + r*A_LDQ + c4) =
            make_float4(cvt_tf32(v.x-h0), cvt_tf32(v.y-h1), cvt_tf32(v.z-h2), cvt_tf32(v.w-h3));
    }
    if (tid < 64) { mrow[tid] = -1e30f; lrow[tid] = 0.f; }

    float oacc[8][4];
#pragma unroll
    for (int j = 0; j < 8; j++)
#pragma unroll
        for (int c = 0; c < 4; c++) oacc[j][c] = 0.f;

    const int r0 = wm + g2, r1 = r0 + 8;

    for (int kt = 0; kt <= qt; kt++) {
        __syncthreads();          // prev PV done, stats updated
        // stage K (hi/lo) and V (tf32)
#pragma unroll
        for (int it = 0; it < 8; it++) {
            int lin = tid + (it << 8);
            int r = lin >> 5, c4 = (lin & 31) << 2;
            const float* krow = kv + (tok0 + (kt<<6) + r) * 2048 + hoff;
            float4 kvv = *(const float4*)(krow + c4);
            float4 vv  = *(const float4*)(krow + 1024 + c4);
            float h0 = cvt_tf32(kvv.x), h1 = cvt_tf32(kvv.y);
            float h2 = cvt_tf32(kvv.z), h3 = cvt_tf32(kvv.w);
            *(float4*)(Kh + r*A_LDQ + c4) = make_float4(h0, h1, h2, h3);
            *(float4*)(Kl + r*A_LDQ + c4) =
                make_float4(cvt_tf32(kvv.x-h0), cvt_tf32(kvv.y-h1),
                            cvt_tf32(kvv.z-h2), cvt_tf32(kvv.w-h3));
            *(float4*)(Vt + r*A_LDV + c4) =
                make_float4(cvt_tf32(vv.x), cvt_tf32(vv.y), cvt_tf32(vv.z), cvt_tf32(vv.w));
        }
        __syncthreads();
        // S = Q K^T (3-pass tf32)
        float sacc[4][4];
#pragma unroll
        for (int j = 0; j < 4; j++)
#pragma unroll
            for (int c = 0; c < 4; c++) sacc[j][c] = 0.f;
#pragma unroll
        for (int kk = 0; kk < 16; kk++) {
            int kc = (kk << 3) + t4;
            int ar0 = r0 * A_LDQ, ar1 = r1 * A_LDQ;
            float ah0 = Qh[ar0+kc], ah1 = Qh[ar1+kc], ah2 = Qh[ar0+kc+4], ah3 = Qh[ar1+kc+4];
            float al0 = Ql[ar0+kc], al1 = Ql[ar1+kc], al2 = Ql[ar0+kc+4], al3 = Ql[ar1+kc+4];
#pragma unroll
            for (int j = 0; j < 4; j++) {
                int br = ((wn<<5) + (j<<3) + g2) * A_LDQ;
                float bh0 = Kh[br+kc], bh1 = Kh[br+kc+4];
                float bl0 = Kl[br+kc], bl1 = Kl[br+kc+4];
                mma8(sacc[j], ah0, ah1, ah2, ah3, bh0, bh1);
                mma8(sacc[j], ah0, ah1, ah2, ah3, bl0, bl1);
                mma8(sacc[j], al0, al1, al2, al3, bh0, bh1);
            }
        }
#pragma unroll
        for (int j = 0; j < 4; j++)
#pragma unroll
            for (int c = 0; c < 4; c++) sacc[j][c] *= SCALE_F;
        if (kt == qt) {
            int grow0 = qbase + r0, grow1 = qbase + r1;
#pragma unroll
            for (int j = 0; j < 4; j++) {
                int col = (kt<<6) + (wn<<5) + (j<<3) + (t4<<1);
                if (col   > grow0) sacc[j][0] = -1e30f;
                if (col+1 > grow0) sacc[j][1] = -1e30f;
                if (col   > grow1) sacc[j][2] = -1e30f;
                if (col+1 > grow1) sacc[j][3] = -1e30f;
            }
        }
        // warp row-max over this warp's 32 cols
        float mx0 = fmaxf(fmaxf(sacc[0][0], sacc[0][1]), fmaxf(sacc[1][0], sacc[1][1]));
        mx0 = fmaxf(mx0, fmaxf(fmaxf(sacc[2][0], sacc[2][1]), fmaxf(sacc[3][0], sacc[3][1])));
        float mx1 = fmaxf(fmaxf(sacc[0][2], sacc[0][3]), fmaxf(sacc[1][2], sacc[1][3]));
        mx1 = fmaxf(mx1, fmaxf(fmaxf(sacc[2][2], sacc[2][3]), fmaxf(sacc[3][2], sacc[3][3])));
        mx0 = fmaxf(mx0, __shfl_xor_sync(0xffffffffu, mx0, 1));
        mx0 = fmaxf(mx0, __shfl_xor_sync(0xffffffffu, mx0, 2));
        mx1 = fmaxf(mx1, __shfl_xor_sync(0xffffffffu, mx1, 1));
        mx1 = fmaxf(mx1, __shfl_xor_sync(0xffffffffu, mx1, 2));
        if (t4 == 0) { red[(r0<<1) + wn] = mx0; red[(r1<<1) + wn] = mx1; }
        __syncthreads();
        // softmax: P, partial sums, O rescale
        float mo0 = mrow[r0], mo1 = mrow[r1];
        float mn0 = fmaxf(mo0, fmaxf(red[r0<<1], red[(r0<<1)+1]));
        float mn1 = fmaxf(mo1, fmaxf(red[r1<<1], red[(r1<<1)+1]));
        float f0 = __expf(mo0 - mn0), f1 = __expf(mo1 - mn1);
        float ps0 = 0.f, ps1 = 0.f;
#pragma unroll
        for (int j = 0; j < 4; j++) {
            float p0 = __expf(sacc[j][0] - mn0), p1 = __expf(sacc[j][1] - mn0);
            float p2 = __expf(sacc[j][2] - mn1), p3 = __expf(sacc[j][3] - mn1);
            ps0 += p0 + p1; ps1 += p2 + p3;
            int pc = (wn<<5) + (j<<3) + (t4<<1);
            *(float2*)(Ps + r0*A_LDP + pc) = make_float2(cvt_tf32(p0), cvt_tf32(p1));
            *(float2*)(Ps + r1*A_LDP + pc) = make_float2(cvt_tf32(p2), cvt_tf32(p3));
        }
        ps0 += __shfl_xor_sync(0xffffffffu, ps0, 1);
        ps0 += __shfl_xor_sync(0xffffffffu, ps0, 2);
        ps1 += __shfl_xor_sync(0xffffffffu, ps1, 1);
        ps1 += __shfl_xor_sync(0xffffffffu, ps1, 2);
        if (t4 == 0) { red2[(r0<<1) + wn] = ps0; red2[(r1<<1) + wn] = ps1; }
#pragma unroll
        for (int j = 0; j < 8; j++) {
            oacc[j][0] *= f0; oacc[j][1] *= f0;
            oacc[j][2] *= f1; oacc[j][3] *= f1;
        }
        __syncthreads();
        if (wn == 0 && t4 == 0) {
            mrow[r0] = mn0; lrow[r0] = lrow[r0] * f0 + red2[r0<<1] + red2[(r0<<1)+1];
            mrow[r1] = mn1; lrow[r1] = lrow[r1] * f1 + red2[r1<<1] + red2[(r1<<1)+1];
        }
        // O += P V (1-pass tf32)
#pragma unroll
        for (int kk = 0; kk < 8; kk++) {
            int kc = (kk << 3) + t4;
            float a0 = Ps[r0*A_LDP + kc], a1 = Ps[r1*A_LDP + kc];
            float a2 = Ps[r0*A_LDP + kc + 4], a3 = Ps[r1*A_LDP + kc + 4];
#pragma unroll
            for (int j = 0; j < 8; j++) {
                int bc = (wn<<6) + (j<<3) + g2;
                float b0 = Vt[kc*A_LDV + bc];
                float b1 = Vt[(kc+4)*A_LDV + bc];
                mma8(oacc[j], a0, a1, a2, a3, b0, b1);
            }
        }
    }
    __syncthreads();
    float il0 = 1.f / lrow[r0], il1 = 1.f / lrow[r1];
#pragma unroll
    for (int j = 0; j < 8; j++) {
        int col = hoff + (wn<<6) + (j<<3) + (t4<<1);
        *(float2*)(o + (tok0 + qbase + r0) * 1024 + col) =
            make_float2(oacc[j][0]*il0, oacc[j][1]*il0);
        *(float2*)(o + (tok0 + qbase + r1) * 1024 + col) =
            make_float2(oacc[j][2]*il1, oacc[j][3]*il1);
    }
}

// ---------------- MoE gate ---------------
__global__ void gate_kernel(const float* __restrict__ h2, const float* __restrict__ gw) {
    int t = blockIdx.x;
    int w = threadIdx.x >> 5, lane = threadIdx.x & 31;
    const float* xr = h2 + (size_t)t * HD;
    const float* gr = gw + (size_t)w * HD;
    float ss = 0.f;
    for (int i = lane; i < HD; i += 32) ss += xr[i] * gr[i];
#pragma unroll
    for (int o = 16; o > 0; o >>= 1) ss += __shfl_down_sync(0xffffffffu, ss, o);
    __shared__ float lg[NEXP];
    if (lane == 0) lg[w] = ss;
    __syncthreads();
    if (threadIdx.x == 0) {
        int i1 = 0;
#pragma unroll
        for (int e = 1; e < NEXP; e++) if (lg[e] > lg[i1]) i1 = e;
        int i2 = (i1 == 0) ? 1 : 0;
#pragma unroll
        for (int e = 0; e < NEXP; e++) if (e != i1 && lg[e] > lg[i2]) i2 = e;
        float e2 = expf(lg[i2] - lg[i1]);
        float inv = 1.f / (1.f + e2);
        g_topi[2*t]   = i1; g_topw[2*t]   = inv;
        g_topi[2*t+1] = i2; g_topw[2*t+1] = e2 * inv;
    }
}

// ---------------- deterministic expert grouping --------------------------
__global__ void route_group_kernel() {
    __shared__ int hist[NEXP * 256];
    __shared__ int soff[NEXP + 1];
    __shared__ int stot[NEXP];
    int tid = threadIdx.x;
    int t0 = tid * 8;
    int lc[NEXP];
#pragma unroll
    for (int e = 0; e < NEXP; e++) lc[e] = 0;
    for (int t = t0; t < t0 + 8; t++) {
        lc[g_topi[2*t]]++; lc[g_topi[2*t+1]]++;
    }
#pragma unroll
    for (int e = 0; e < NEXP; e++) hist[e * 256 + tid] = lc[e];
    __syncthreads();
    if (tid < NEXP) {
        int a = 0;
        for (int i = 0; i < 256; i++) { int v = hist[tid*256+i]; hist[tid*256+i] = a; a += v; }
        stot[tid] = a;
    }
    __syncthreads();
    if (tid == 0) {
        int a = 0;
        for (int e = 0; e < NEXP; e++) { soff[e] = a; g_off[e] = a; g_cnt[e] = stot[e]; a += stot[e]; }
        soff[NEXP] = a;
    }
    __syncthreads();
    int pos[NEXP];
#pragma unroll
    for (int e = 0; e < NEXP; e++) pos[e] = soff[e] + hist[e * 256 + tid];
    for (int t = t0; t < t0 + 8; t++) {
        for (int s2 = 0; s2 < 2; s2++) {
            int e = g_topi[2*t + s2];
            int p = pos[e]++;
            g_ptok[p] = t; g_pdst[p] = 2*t + s2; g_pscale[p] = g_topw[2*t + s2];
        }
    }
}

// ---------------- elementwise tails --------------------------------------
__global__ void swiglu_kernel(const float* __restrict__ gu, float* __restrict__ act) {
    int t = blockIdx.x, i = threadIdx.x;
    float4 g = *(const float4*)(gu + (size_t)t*2048 + 4*i);
    float4 u = *(const float4*)(gu + (size_t)t*2048 + 1024 + 4*i);
    float4 r;
    r.x = g.x / (1.f + expf(-g.x)) * u.x;
    r.y = g.y / (1.f + expf(-g.y)) * u.y;
    r.z = g.z / (1.f + expf(-g.z)) * u.z;
    r.w = g.w / (1.f + expf(-g.w)) * u.w;
    *(float4*)(act + (size_t)t*HD + 4*i) = r;
}

__global__ void add_routed_kernel(float* __restrict__ out) {
    int t = blockIdx.x, i = threadIdx.x;
    float4 a = *(const float4*)(out + (size_t)t*HD + 4*i);
    float4 y0 = *(const float4*)(g_ybuf + (size_t)(2*t)*HD + 4*i);
    float4 y1 = *(const float4*)(g_ybuf + (size_t)(2*t+1)*HD + 4*i);
    a.x += y0.x + y1.x; a.y += y0.y + y1.y; a.z += y0.z + y1.z; a.w += y0.w + y1.w;
    *(float4*)(out + (size_t)t*HD + 4*i) = a;
}

// ---------------- launch ---------------------------------------------------
extern "C" void kernel_launch(void* const* d_in, const int* in_sizes, int n_in,
                              void* d_out, int out_size) {
    const float* x    = (const float*)d_in[0];
    const float* ln1  = (const float*)d_in[2];
    const float* ln2  = (const float*)d_in[3];
    const float* Wq   = (const float*)d_in[4];
    const float* Wkv  = (const float*)d_in[5];
    const float* Wo   = (const float*)d_in[6];
    const float* gate = (const float*)d_in[7];
    const float* w1   = (const float*)d_in[8];
    const float* w2   = (const float*)d_in[9];
    const float* sgu  = (const float*)d_in[10];
    const float* sdwn = (const float*)d_in[11];
    float* out = (float*)d_out;

    float *p_wqp, *p_h, *p_q, *p_kv, *p_attn, *p_x2, *p_h2, *p_gu, *p_act, *p_he;
    cudaGetSymbolAddress((void**)&p_wqp,  g_wqp);
    cudaGetSymbolAddress((void**)&p_h,    g_h);
    cudaGetSymbolAddress((void**)&p_q,    g_q);
    cudaGetSymbolAddress((void**)&p_kv,   g_kv);
    cudaGetSymbolAddress((void**)&p_attn, g_attn);
    cudaGetSymbolAddress((void**)&p_x2,   g_x2);
    cudaGetSymbolAddress((void**)&p_h2,   g_h2);
    cudaGetSymbolAddress((void**)&p_gu,   g_gu);
    cudaGetSymbolAddress((void**)&p_act,  g_act);
    cudaGetSymbolAddress((void**)&p_he,   g_he);

    const int ATTN2_SMEM = ATTN2_FLOATS * 4;
    cudaFuncSetAttribute(attn_tc_kernel, cudaFuncAttributeMaxDynamicSharedMemorySize, ATTN2_SMEM);
    const int SM_P1 = 2 * 2 * MATF * 4;   // 69632 B
    const int SM_P3 = 2 * 4 * MATF * 4;   // 139264 B
    cudaFuncSetAttribute(gemm_tc<3,0>, cudaFuncAttributeMaxDynamicSharedMemorySize, SM_P3);
    cudaFuncSetAttribute(gemm_tc<3,1>, cudaFuncAttributeMaxDynamicSharedMemorySize, SM_P3);
    cudaFuncSetAttribute(gemm_tc<1,0>, cudaFuncAttributeMaxDynamicSharedMemorySize, SM_P1);
    cudaFuncSetAttribute(gemm_tc<1,1>, cudaFuncAttributeMaxDynamicSharedMemorySize, SM_P1);
    cudaFuncSetAttribute(gemm_tc<1,2>, cudaFuncAttributeMaxDynamicSharedMemorySize, SM_P1);
    cudaFuncSetAttribute(gemm_tc<1,3>, cudaFuncAttributeMaxDynamicSharedMemorySize, SM_P1);

    // attention block (routing-critical: tf32 3-pass = ~fp32 precision)
    pack_wq_kernel<<<1024, 256>>>(Wq, p_wqp);
    rmsnorm_kernel<<<TT, 256>>>(x, ln1, p_h);
    gemm_tc<3,0><<<dim3(8, 16), 256, SM_P3>>>(p_h, p_wqp, p_q,  nullptr, 1024, 1024, 1024, 1024);
    gemm_tc<3,0><<<dim3(16,16), 256, SM_P3>>>(p_h, Wkv,   p_kv, nullptr, 1024, 1024, 1024, 2048);
    attn_tc_kernel<<<dim3(16, NH, 2), 256, ATTN2_SMEM>>>(p_q, p_kv, p_attn);
    gemm_tc<3,1><<<dim3(8, 16), 256, SM_P3>>>(p_attn, Wo, p_x2, x, 1024, 1024, 1024, 1024);

    // MoE block
    rmsnorm_kernel<<<TT, 256>>>(p_x2, ln2, p_h2);
    gate_kernel<<<TT, 256>>>(p_h2, gate);
    route_group_kernel<<<1, 256>>>();
    gemm_tc<1,2><<<dim3(8, 16, NEXP), 256, SM_P1>>>(p_h2, w1, nullptr, nullptr, 1024, 1024, 1024, 1024);
    gemm_tc<1,3><<<dim3(8, 16, NEXP), 256, SM_P1>>>(p_he, w2, nullptr, nullptr, 1024, 1024, 1024, 1024);

    // shared expert
    gemm_tc<1,0><<<dim3(16,16), 256, SM_P1>>>(p_h2, sgu, p_gu, nullptr, 1024, 1024, 1024, 2048);
    swiglu_kernel<<<TT, 256>>>(p_gu, p_act);
    gemm_tc<1,1><<<dim3(8, 16), 256, SM_P1>>>(p_act, sdwn, out, p_x2, 1024, 1024, 1024, 1024);

    // combine routed experts
    add_routed_kernel<<<TT, 256>>>(out);
}

// round 5
// speedup vs baseline: 2.4916x; 1.5223x over previous
#include <cuda_runtime.h>
#include <stdint.h>
#include <math.h>

#define TT    2048
#define HD    1024
#define NH    8
#define SEQ   1024
#define NEXP  8
#define SCALE_F 0.07216878364870322f   // 192^-0.5

// ---------------- scratch ----------------
__device__ float g_wq_hi [1024*1024];
__device__ float g_wq_lo [1024*1024];
__device__ float g_wkv_hi[2048*1024];
__device__ float g_wkv_lo[2048*1024];
__device__ float g_wo_hi [1024*1024];
__device__ float g_wo_lo [1024*1024];
__device__ float g_h_hi  [TT*HD];
__device__ float g_h_lo  [TT*HD];
__device__ float g_o_hi  [TT*1024];
__device__ float g_o_lo  [TT*1024];
__device__ float g_q     [TT*1024];
__device__ float g_kv    [TT*2048];
__device__ float g_x2    [TT*HD];
__device__ float g_h2    [TT*HD];
__device__ float g_gu    [TT*2048];
__device__ float g_act   [TT*1024];
__device__ float g_he    [2*TT*1024];
__device__ float g_ybuf  [2*TT*1024];
__device__ float g_topw  [2*TT];
__device__ float g_pscale[2*TT];
__device__ int   g_topi[2*TT];
__device__ int   g_ptok[2*TT];
__device__ int   g_pdst[2*TT];
__device__ int   g_cnt [NEXP];
__device__ int   g_off [NEXP];

// ---------------- helpers ----------------
__device__ __forceinline__ float cvt_tf32(float x) {
    unsigned u; asm("cvt.rna.tf32.f32 %0, %1;" : "=r"(u) : "f"(x));
    return __uint_as_float(u);
}
__device__ __forceinline__ void mma8(float* d, float a0, float a1, float a2, float a3,
                                     float b0, float b1) {
    unsigned A0=__float_as_uint(a0), A1=__float_as_uint(a1);
    unsigned A2=__float_as_uint(a2), A3=__float_as_uint(a3);
    unsigned B0=__float_as_uint(b0), B1=__float_as_uint(b1);
    asm volatile("mma.sync.aligned.m16n8k8.row.col.f32.tf32.tf32.f32 "
                 "{%0,%1,%2,%3},{%4,%5,%6,%7},{%8,%9},{%0,%1,%2,%3};"
                 : "+f"(d[0]), "+f"(d[1]), "+f"(d[2]), "+f"(d[3])
                 : "r"(A0), "r"(A1), "r"(A2), "r"(A3), "r"(B0), "r"(B1));
}
__device__ __forceinline__ void cp16(uint32_t s, const float* g) {
    asm volatile("cp.async.cg.shared.global [%0], [%1], 16;" :: "r"(s), "l"(g));
}
__device__ __forceinline__ void cpcommit() { asm volatile("cp.async.commit_group;"); }
template<int N> __device__ __forceinline__ void cpwait() {
    asm volatile("cp.async.wait_group %0;" :: "n"(N));
}

// ---------------- pack Wq (nope rows only) + hi/lo split ------------------
__global__ void pack_wq_kernel(const float* __restrict__ Wq,
                               float* __restrict__ hi, float* __restrict__ lo) {
    int r = blockIdx.x;
    int h = r >> 7, d = r & 127;
    float4 v = ((const float4*)(Wq + (size_t)(h*192 + d) * HD))[threadIdx.x];
    float h0=cvt_tf32(v.x), h1=cvt_tf32(v.y), h2=cvt_tf32(v.z), h3=cvt_tf32(v.w);
    ((float4*)(hi + (size_t)r * HD))[threadIdx.x] = make_float4(h0,h1,h2,h3);
    ((float4*)(lo + (size_t)r * HD))[threadIdx.x] =
        make_float4(cvt_tf32(v.x-h0), cvt_tf32(v.y-h1), cvt_tf32(v.z-h2), cvt_tf32(v.w-h3));
}

// ---------------- generic hi/lo split (1024 els per block) ----------------
__global__ void split_kernel(const float* __restrict__ src,
                             float* __restrict__ hi, float* __restrict__ lo) {
    size_t i = ((size_t)blockIdx.x * 256 + threadIdx.x) * 4;
    float4 v = *(const float4*)(src + i);
    float h0=cvt_tf32(v.x), h1=cvt_tf32(v.y), h2=cvt_tf32(v.z), h3=cvt_tf32(v.w);
    *(float4*)(hi + i) = make_float4(h0,h1,h2,h3);
    *(float4*)(lo + i) =
        make_float4(cvt_tf32(v.x-h0), cvt_tf32(v.y-h1), cvt_tf32(v.z-h2), cvt_tf32(v.w-h3));
}

// ---------------- rmsnorm (SPLIT=1: write hi/lo; 0: fp32) -----------------
template<int SPLIT>
__global__ void rmsnorm_kernel(const float* __restrict__ x, const float* __restrict__ w,
                               float* __restrict__ out, float* __restrict__ out_lo) {
    int t = blockIdx.x;
    const float* xr = x + (size_t)t * HD;
    float ss = 0.f;
    for (int i = threadIdx.x; i < HD; i += 256) { float v = xr[i]; ss += v * v; }
    __shared__ float red[256];
    red[threadIdx.x] = ss; __syncthreads();
    for (int o = 128; o > 0; o >>= 1) {
        if (threadIdx.x < o) red[threadIdx.x] += red[threadIdx.x + o];
        __syncthreads();
    }
    float inv = rsqrtf(red[0] * (1.f / HD) + 1e-6f);
    for (int i = threadIdx.x; i < HD; i += 256) {
        float v = xr[i] * inv * w[i];
        if (SPLIT) {
            float h = cvt_tf32(v);
            out[(size_t)t * HD + i] = h;
            out_lo[(size_t)t * HD + i] = cvt_tf32(v - h);
        } else {
            out[(size_t)t * HD + i] = v;
        }
    }
}

// ---------------- cp.async tensor-core GEMM (NT) --------------------------
// P=1: single-pass tf32 (raw fp32 in smem, HW truncation in mma)
// P=3: 3-pass tf32 from pre-split hi/lo streams
// MODE: 0 plain, 1 +residual, 2 expert1 (gather+SiLU->g_he), 3 expert2 (scatter)
#define KC  32
#define LDR 36
#define MATS (128*LDR)
template<int P, int MODE>
__global__ void __launch_bounds__(256, (P==1)?2:1)
gemm_cp(const float* __restrict__ Ah_, const float* __restrict__ Al_,
        const float* __restrict__ Bh_, const float* __restrict__ Bl_,
        float* __restrict__ C, const float* __restrict__ R,
        int K, int lda, int ldb, int ldc) {
    extern __shared__ float smf[];
    const int SST = ((P==3)?4:2) * MATS;
    const int bm = blockIdx.y << 7, bn = blockIdx.x << 7;
    int off = 0, cnt = 0x7fffffff;
    const float* Bh = Bh_;
    if (MODE >= 2) {
        int e = blockIdx.z;
        cnt = g_cnt[e];
        if (cnt == 0 || bm >= cnt) return;
        off = g_off[e];
        Bh = Bh_ + (size_t)e * 1024 * 1024;
    }
    __shared__ int rowA[128];
    const int tid = threadIdx.x;
    if (MODE >= 2) {
        if (tid < 128) {
            int gr = bm + tid; if (gr >= cnt) gr = cnt - 1;
            rowA[tid] = (MODE == 2) ? g_ptok[off + gr] : (off + gr);
        }
        __syncthreads();
    }
    const int lane = tid & 31, w = tid >> 5;
    const int g2 = lane >> 2, t4 = lane & 3;
    const int wm = (w >> 2) << 6, wn = (w & 3) << 5;
    const int seg = (tid & 7) << 2, rb = tid >> 3;
    uint32_t sbase = (uint32_t)__cvta_generic_to_shared(smf);

    auto fill = [&](int st, int k0) {
        uint32_t s0 = sbase + (uint32_t)(st * SST) * 4u;
#pragma unroll
        for (int i = 0; i < 4; i++) {
            int row = rb + (i << 5);
            uint32_t so = (uint32_t)(row * LDR + seg) * 4u;
            const float* ga;
            if (MODE >= 2) ga = Ah_ + (size_t)rowA[row] * lda + k0 + seg;
            else           ga = Ah_ + (size_t)(bm + row) * lda + k0 + seg;
            cp16(s0 + so, ga);
            if (P == 3)
                cp16(s0 + (uint32_t)MATS*4u + so, Al_ + (size_t)(bm + row) * lda + k0 + seg);
            cp16(s0 + (uint32_t)((P==3?2:1)*MATS)*4u + so,
                 Bh + (size_t)(bn + row) * ldb + k0 + seg);
            if (P == 3)
                cp16(s0 + (uint32_t)(3*MATS)*4u + so, Bl_ + (size_t)(bn + row) * ldb + k0 + seg);
        }
        cpcommit();
    };

    float acc[4][4][4];
#pragma unroll
    for (int i = 0; i < 4; i++)
#pragma unroll
        for (int j = 0; j < 4; j++)
#pragma unroll
            for (int q = 0; q < 4; q++) acc[i][j][q] = 0.f;

    auto compute = [&](int st) {
        const float* SA  = smf + st * SST;
        const float* SAl = SA + MATS;
        const float* SB  = SA + ((P==3)?2:1) * MATS;
        const float* SBl = SA + 3 * MATS;
#pragma unroll
        for (int kb = 0; kb < 4; kb++) {
            int kc = (kb << 3) + t4;
            float ah[4][4], al[4][4], bh[4][2], bl[4][2];
#pragma unroll
            for (int i = 0; i < 4; i++) {
                int m = (wm + (i << 4) + g2) * LDR;
                ah[i][0] = SA[m + kc];            ah[i][1] = SA[m + (LDR<<3) + kc];
                ah[i][2] = SA[m + kc + 4];        ah[i][3] = SA[m + (LDR<<3) + kc + 4];
                if (P == 3) {
                    al[i][0] = SAl[m + kc];       al[i][1] = SAl[m + (LDR<<3) + kc];
                    al[i][2] = SAl[m + kc + 4];   al[i][3] = SAl[m + (LDR<<3) + kc + 4];
                }
            }
#pragma unroll
            for (int j = 0; j < 4; j++) {
                int n = (wn + (j << 3) + g2) * LDR;
                bh[j][0] = SB[n + kc];  bh[j][1] = SB[n + kc + 4];
                if (P == 3) { bl[j][0] = SBl[n + kc]; bl[j][1] = SBl[n + kc + 4]; }
            }
#pragma unroll
            for (int i = 0; i < 4; i++)
#pragma unroll
                for (int j = 0; j < 4; j++) {
                    mma8(acc[i][j], ah[i][0],ah[i][1],ah[i][2],ah[i][3], bh[j][0],bh[j][1]);
                    if (P == 3) {
                        mma8(acc[i][j], ah[i][0],ah[i][1],ah[i][2],ah[i][3], bl[j][0],bl[j][1]);
                        mma8(acc[i][j], al[i][0],al[i][1],al[i][2],al[i][3], bh[j][0],bh[j][1]);
                    }
                }
        }
    };

    fill(0, 0);
    const int NS = K >> 5;
    for (int ks = 0; ks < NS; ks++) {
        if (ks + 1 < NS) { fill((ks + 1) & 1, (ks + 1) << 5); cpwait<1>(); }
        else cpwait<0>();
        __syncthreads();
        compute(ks & 1);
        __syncthreads();
    }

    // epilogue
#pragma unroll
    for (int i = 0; i < 4; i++) {
#pragma unroll
        for (int j = 0; j < 4; j++) {
            int m0 = bm + wm + 16*i + g2, m1 = m0 + 8;
            int nc = bn + wn + 8*j + 2*t4;
            float2 v0 = make_float2(acc[i][j][0], acc[i][j][1]);
            float2 v1 = make_float2(acc[i][j][2], acc[i][j][3]);
            if (MODE == 0 || MODE == 1) {
                size_t o0 = (size_t)m0 * ldc + nc, o1 = (size_t)m1 * ldc + nc;
                if (MODE == 1) {
                    float2 r0 = *(const float2*)(R + o0);
                    float2 r1 = *(const float2*)(R + o1);
                    v0.x += r0.x; v0.y += r0.y; v1.x += r1.x; v1.y += r1.y;
                }
                *(float2*)(C + o0) = v0;
                *(float2*)(C + o1) = v1;
            } else if (MODE == 2) {
                if (m0 < cnt) {
                    float2 s = make_float2(v0.x/(1.f+expf(-v0.x)), v0.y/(1.f+expf(-v0.y)));
                    *(float2*)(g_he + (size_t)(off+m0)*1024 + nc) = s;
                }
                if (m1 < cnt) {
                    float2 s = make_float2(v1.x/(1.f+expf(-v1.x)), v1.y/(1.f+expf(-v1.y)));
                    *(float2*)(g_he + (size_t)(off+m1)*1024 + nc) = s;
                }
            } else {
                if (m0 < cnt) {
                    int p = off + m0; float sc = g_pscale[p]; int d = g_pdst[p];
                    *(float2*)(g_ybuf + (size_t)d*1024 + nc) = make_float2(v0.x*sc, v0.y*sc);
                }
                if (m1 < cnt) {
                    int p = off + m1; float sc = g_pscale[p]; int d = g_pdst[p];
                    *(float2*)(g_ybuf + (size_t)d*1024 + nc) = make_float2(v1.x*sc, v1.y*sc);
                }
            }
        }
    }
}

// ---------------- flash attention: tensor-core tf32 ----------------------
#define A_LDQ 132
#define A_LDV 136
#define A_LDP 68
#define ATTN2_FLOATS (4*64*A_LDQ + 64*A_LDV + 64*A_LDP + 128 + 128 + 64 + 64)
__global__ void __launch_bounds__(256, 1) attn_tc_kernel(const float* __restrict__ q,
                                                         const float* __restrict__ kv,
                                                         float* __restrict__ ohi,
                                                         float* __restrict__ olo) {
    extern __shared__ float sm[];
    float* Qh   = sm;
    float* Ql   = Qh + 64*A_LDQ;
    float* Kh   = Ql + 64*A_LDQ;
    float* Kl   = Kh + 64*A_LDQ;
    float* Vt   = Kl + 64*A_LDQ;
    float* Ps   = Vt + 64*A_LDV;
    float* red  = Ps + 64*A_LDP;
    float* red2 = red + 128;
    float* mrow = red2 + 128;
    float* lrow = mrow + 64;

    const int qt = 15 - blockIdx.x;
    const int head = blockIdx.y, b = blockIdx.z;
    const int tid = threadIdx.x, lane = tid & 31, wid = tid >> 5;
    const int g2 = lane >> 2, t4 = lane & 3;
    const int wm = (wid & 3) << 4;
    const int wn = wid >> 2;
    const int qbase = qt << 6;
    const size_t tok0 = (size_t)b * SEQ;
    const int hoff = head << 7;

#pragma unroll
    for (int it = 0; it < 8; it++) {
        int lin = tid + (it << 8);
        int r = lin >> 5, c4 = (lin & 31) << 2;
        float4 v = *(const float4*)(q + (tok0 + qbase + r) * 1024 + hoff + c4);
        float h0 = cvt_tf32(v.x), h1 = cvt_tf32(v.y), h2 = cvt_tf32(v.z), h3 = cvt_tf32(v.w);
        *(float4*)(Qh + r*A_LDQ + c4) = make_float4(h0, h1, h2, h3);
        *(float4*)(Ql + r*A_LDQ + c4) =
            make_float4(cvt_tf32(v.x-h0), cvt_tf32(v.y-h1), cvt_tf32(v.z-h2), cvt_tf32(v.w-h3));
    }
    if (tid < 64) { mrow[tid] = -1e30f; lrow[tid] = 0.f; }

    float oacc[8][4];
#pragma unroll
    for (int j = 0; j < 8; j++)
#pragma unroll
        for (int c = 0; c < 4; c++) oacc[j][c] = 0.f;

    const int r0 = wm + g2, r1 = r0 + 8;

    for (int kt = 0; kt <= qt; kt++) {
        __syncthreads();
#pragma unroll
        for (int it = 0; it < 8; it++) {
            int lin = tid + (it << 8);
            int r = lin >> 5, c4 = (lin & 31) << 2;
            const float* krow = kv + (tok0 + (kt<<6) + r) * 2048 + hoff;
            float4 kvv = *(const float4*)(krow + c4);
            float4 vv  = *(const float4*)(krow + 1024 + c4);
            float h0 = cvt_tf32(kvv.x), h1 = cvt_tf32(kvv.y);
            float h2 = cvt_tf32(kvv.z), h3 = cvt_tf32(kvv.w);
            *(float4*)(Kh + r*A_LDQ + c4) = make_float4(h0, h1, h2, h3);
            *(float4*)(Kl + r*A_LDQ + c4) =
                make_float4(cvt_tf32(kvv.x-h0), cvt_tf32(kvv.y-h1),
                            cvt_tf32(kvv.z-h2), cvt_tf32(kvv.w-h3));
            *(float4*)(Vt + r*A_LDV + c4) =
                make_float4(cvt_tf32(vv.x), cvt_tf32(vv.y), cvt_tf32(vv.z), cvt_tf32(vv.w));
        }
        __syncthreads();
        float sacc[4][4];
#pragma unroll
        for (int j = 0; j < 4; j++)
#pragma unroll
            for (int c = 0; c < 4; c++) sacc[j][c] = 0.f;
#pragma unroll
        for (int kk = 0; kk < 16; kk++) {
            int kc = (kk << 3) + t4;
            int ar0 = r0 * A_LDQ, ar1 = r1 * A_LDQ;
            float ah0 = Qh[ar0+kc], ah1 = Qh[ar1+kc], ah2 = Qh[ar0+kc+4], ah3 = Qh[ar1+kc+4];
            float al0 = Ql[ar0+kc], al1 = Ql[ar1+kc], al2 = Ql[ar0+kc+4], al3 = Ql[ar1+kc+4];
#pragma unroll
            for (int j = 0; j < 4; j++) {
                int br = ((wn<<5) + (j<<3) + g2) * A_LDQ;
                float bh0 = Kh[br+kc], bh1 = Kh[br+kc+4];
                float bl0 = Kl[br+kc], bl1 = Kl[br+kc+4];
                mma8(sacc[j], ah0, ah1, ah2, ah3, bh0, bh1);
                mma8(sacc[j], ah0, ah1, ah2, ah3, bl0, bl1);
                mma8(sacc[j], al0, al1, al2, al3, bh0, bh1);
            }
        }
#pragma unroll
        for (int j = 0; j < 4; j++)
#pragma unroll
            for (int c = 0; c < 4; c++) sacc[j][c] *= SCALE_F;
        if (kt == qt) {
            int grow0 = qbase + r0, grow1 = qbase + r1;
#pragma unroll
            for (int j = 0; j < 4; j++) {
                int col = (kt<<6) + (wn<<5) + (j<<3) + (t4<<1);
                if (col   > grow0) sacc[j][0] = -1e30f;
                if (col+1 > grow0) sacc[j][1] = -1e30f;
                if (col   > grow1) sacc[j][2] = -1e30f;
                if (col+1 > grow1) sacc[j][3] = -1e30f;
            }
        }
        float mx0 = fmaxf(fmaxf(sacc[0][0], sacc[0][1]), fmaxf(sacc[1][0], sacc[1][1]));
        mx0 = fmaxf(mx0, fmaxf(fmaxf(sacc[2][0], sacc[2][1]), fmaxf(sacc[3][0], sacc[3][1])));
        float mx1 = fmaxf(fmaxf(sacc[0][2], sacc[0][3]), fmaxf(sacc[1][2], sacc[1][3]));
        mx1 = fmaxf(mx1, fmaxf(fmaxf(sacc[2][2], sacc[2][3]), fmaxf(sacc[3][2], sacc[3][3])));
        mx0 = fmaxf(mx0, __shfl_xor_sync(0xffffffffu, mx0, 1));
        mx0 = fmaxf(mx0, __shfl_xor_sync(0xffffffffu, mx0, 2));
        mx1 = fmaxf(mx1, __shfl_xor_sync(0xffffffffu, mx1, 1));
        mx1 = fmaxf(mx1, __shfl_xor_sync(0xffffffffu, mx1, 2));
        if (t4 == 0) { red[(r0<<1) + wn] = mx0; red[(r1<<1) + wn] = mx1; }
        __syncthreads();
        float mo0 = mrow[r0], mo1 = mrow[r1];
        float mn0 = fmaxf(mo0, fmaxf(red[r0<<1], red[(r0<<1)+1]));
        float mn1 = fmaxf(mo1, fmaxf(red[r1<<1], red[(r1<<1)+1]));
        float f0 = __expf(mo0 - mn0), f1 = __expf(mo1 - mn1);
        float ps0 = 0.f, ps1 = 0.f;
#pragma unroll
        for (int j = 0; j < 4; j++) {
            float p0 = __expf(sacc[j][0] - mn0), p1 = __expf(sacc[j][1] - mn0);
            float p2 = __expf(sacc[j][2] - mn1), p3 = __expf(sacc[j][3] - mn1);
            ps0 += p0 + p1; ps1 += p2 + p3;
            int pc = (wn<<5) + (j<<3) + (t4<<1);
            *(float2*)(Ps + r0*A_LDP + pc) = make_float2(cvt_tf32(p0), cvt_tf32(p1));
            *(float2*)(Ps + r1*A_LDP + pc) = make_float2(cvt_tf32(p2), cvt_tf32(p3));
        }
        ps0 += __shfl_xor_sync(0xffffffffu, ps0, 1);
        ps0 += __shfl_xor_sync(0xffffffffu, ps0, 2);
        ps1 += __shfl_xor_sync(0xffffffffu, ps1, 1);
        ps1 += __shfl_xor_sync(0xffffffffu, ps1, 2);
        if (t4 == 0) { red2[(r0<<1) + wn] = ps0; red2[(r1<<1) + wn] = ps1; }
#pragma unroll
        for (int j = 0; j < 8; j++) {
            oacc[j][0] *= f0; oacc[j][1] *= f0;
            oacc[j][2] *= f1; oacc[j][3] *= f1;
        }
        __syncthreads();
        if (wn == 0 && t4 == 0) {
            mrow[r0] = mn0; lrow[r0] = lrow[r0] * f0 + red2[r0<<1] + red2[(r0<<1)+1];
            mrow[r1] = mn1; lrow[r1] = lrow[r1] * f1 + red2[r1<<1] + red2[(r1<<1)+1];
        }
#pragma unroll
        for (int kk = 0; kk < 8; kk++) {
            int kc = (kk << 3) + t4;
            float a0 = Ps[r0*A_LDP + kc], a1 = Ps[r1*A_LDP + kc];
            float a2 = Ps[r0*A_LDP + kc + 4], a3 = Ps[r1*A_LDP + kc + 4];
#pragma unroll
            for (int j = 0; j < 8; j++) {
                int bc = (wn<<6) + (j<<3) + g2;
                float b0 = Vt[kc*A_LDV + bc];
                float b1 = Vt[(kc+4)*A_LDV + bc];
                mma8(oacc[j], a0, a1, a2, a3, b0, b1);
            }
        }
    }
    __syncthreads();
    float il0 = 1.f / lrow[r0], il1 = 1.f / lrow[r1];
#pragma unroll
    for (int j = 0; j < 8; j++) {
        int col = hoff + (wn<<6) + (j<<3) + (t4<<1);
        size_t o0 = (tok0 + qbase + r0) * 1024 + col;
        size_t o1 = (tok0 + qbase + r1) * 1024 + col;
        float v00 = oacc[j][0]*il0, v01 = oacc[j][1]*il0;
        float v10 = oacc[j][2]*il1, v11 = oacc[j][3]*il1;
        float h00 = cvt_tf32(v00), h01 = cvt_tf32(v01);
        float h10 = cvt_tf32(v10), h11 = cvt_tf32(v11);
        *(float2*)(ohi + o0) = make_float2(h00, h01);
        *(float2*)(ohi + o1) = make_float2(h10, h11);
        *(float2*)(olo + o0) = make_float2(cvt_tf32(v00-h00), cvt_tf32(v01-h01));
        *(float2*)(olo + o1) = make_float2(cvt_tf32(v10-h10), cvt_tf32(v11-h11));
    }
}

// ---------------- MoE gate ---------------
__global__ void gate_kernel(const float* __restrict__ h2, const float* __restrict__ gw) {
    int t = blockIdx.x;
    int w = threadIdx.x >> 5, lane = threadIdx.x & 31;
    const float* xr = h2 + (size_t)t * HD;
    const float* gr = gw + (size_t)w * HD;
    float ss = 0.f;
    for (int i = lane; i < HD; i += 32) ss += xr[i] * gr[i];
#pragma unroll
    for (int o = 16; o > 0; o >>= 1) ss += __shfl_down_sync(0xffffffffu, ss, o);
    __shared__ float lg[NEXP];
    if (lane == 0) lg[w] = ss;
    __syncthreads();
    if (threadIdx.x == 0) {
        int i1 = 0;
#pragma unroll
        for (int e = 1; e < NEXP; e++) if (lg[e] > lg[i1]) i1 = e;
        int i2 = (i1 == 0) ? 1 : 0;
#pragma unroll
        for (int e = 0; e < NEXP; e++) if (e != i1 && lg[e] > lg[i2]) i2 = e;
        float e2 = expf(lg[i2] - lg[i1]);
        float inv = 1.f / (1.f + e2);
        g_topi[2*t]   = i1; g_topw[2*t]   = inv;
        g_topi[2*t+1] = i2; g_topw[2*t+1] = e2 * inv;
    }
}

// ---------------- deterministic expert grouping --------------------------
__global__ void route_group_kernel() {
    __shared__ int hist[NEXP * 256];
    __shared__ int soff[NEXP + 1];
    __shared__ int stot[NEXP];
    int tid = threadIdx.x;
    int t0 = tid * 8;
    int lc[NEXP];
#pragma unroll
    for (int e = 0; e < NEXP; e++) lc[e] = 0;
    for (int t = t0; t < t0 + 8; t++) {
        lc[g_topi[2*t]]++; lc[g_topi[2*t+1]]++;
    }
#pragma unroll
    for (int e = 0; e < NEXP; e++) hist[e * 256 + tid] = lc[e];
    __syncthreads();
    if (tid < NEXP) {
        int a = 0;
        for (int i = 0; i < 256; i++) { int v = hist[tid*256+i]; hist[tid*256+i] = a; a += v; }
        stot[tid] = a;
    }
    __syncthreads();
    if (tid == 0) {
        int a = 0;
        for (int e = 0; e < NEXP; e++) { soff[e] = a; g_off[e] = a; g_cnt[e] = stot[e]; a += stot[e]; }
        soff[NEXP] = a;
    }
    __syncthreads();
    int pos[NEXP];
#pragma unroll
    for (int e = 0; e < NEXP; e++) pos[e] = soff[e] + hist[e * 256 + tid];
    for (int t = t0; t < t0 + 8; t++) {
        for (int s2 = 0; s2 < 2; s2++) {
            int e = g_topi[2*t + s2];
            int p = pos[e]++;
            g_ptok[p] = t; g_pdst[p] = 2*t + s2; g_pscale[p] = g_topw[2*t + s2];
        }
    }
}

// ---------------- elementwise tails --------------------------------------
__global__ void swiglu_kernel(const float* __restrict__ gu, float* __restrict__ act) {
    int t = blockIdx.x, i = threadIdx.x;
    float4 g = *(const float4*)(gu + (size_t)t*2048 + 4*i);
    float4 u = *(const float4*)(gu + (size_t)t*2048 + 1024 + 4*i);
    float4 r;
    r.x = g.x / (1.f + expf(-g.x)) * u.x;
    r.y = g.y / (1.f + expf(-g.y)) * u.y;
    r.z = g.z / (1.f + expf(-g.z)) * u.z;
    r.w = g.w / (1.f + expf(-g.w)) * u.w;
    *(float4*)(act + (size_t)t*HD + 4*i) = r;
}

__global__ void add_routed_kernel(float* __restrict__ out) {
    int t = blockIdx.x, i = threadIdx.x;
    float4 a = *(const float4*)(out + (size_t)t*HD + 4*i);
    float4 y0 = *(const float4*)(g_ybuf + (size_t)(2*t)*HD + 4*i);
    float4 y1 = *(const float4*)(g_ybuf + (size_t)(2*t+1)*HD + 4*i);
    a.x += y0.x + y1.x; a.y += y0.y + y1.y; a.z += y0.z + y1.z; a.w += y0.w + y1.w;
    *(float4*)(out + (size_t)t*HD + 4*i) = a;
}

// ---------------- launch ---------------------------------------------------
extern "C" void kernel_launch(void* const* d_in, const int* in_sizes, int n_in,
                              void* d_out, int out_size) {
    const float* x    = (const float*)d_in[0];
    const float* ln1  = (const float*)d_in[2];
    const float* ln2  = (const float*)d_in[3];
    const float* Wq   = (const float*)d_in[4];
    const float* Wkv  = (const float*)d_in[5];
    const float* Wo   = (const float*)d_in[6];
    const float* gate = (const float*)d_in[7];
    const float* w1   = (const float*)d_in[8];
    const float* w2   = (const float*)d_in[9];
    const float* sgu  = (const float*)d_in[10];
    const float* sdwn = (const float*)d_in[11];
    float* out = (float*)d_out;

    float *p_wq_hi,*p_wq_lo,*p_wkv_hi,*p_wkv_lo,*p_wo_hi,*p_wo_lo;
    float *p_h_hi,*p_h_lo,*p_o_hi,*p_o_lo;
    float *p_q,*p_kv,*p_x2,*p_h2,*p_gu,*p_act,*p_he;
    cudaGetSymbolAddress((void**)&p_wq_hi,  g_wq_hi);
    cudaGetSymbolAddress((void**)&p_wq_lo,  g_wq_lo);
    cudaGetSymbolAddress((void**)&p_wkv_hi, g_wkv_hi);
    cudaGetSymbolAddress((void**)&p_wkv_lo, g_wkv_lo);
    cudaGetSymbolAddress((void**)&p_wo_hi,  g_wo_hi);
    cudaGetSymbolAddress((void**)&p_wo_lo,  g_wo_lo);
    cudaGetSymbolAddress((void**)&p_h_hi,   g_h_hi);
    cudaGetSymbolAddress((void**)&p_h_lo,   g_h_lo);
    cudaGetSymbolAddress((void**)&p_o_hi,   g_o_hi);
    cudaGetSymbolAddress((void**)&p_o_lo,   g_o_lo);
    cudaGetSymbolAddress((void**)&p_q,      g_q);
    cudaGetSymbolAddress((void**)&p_kv,     g_kv);
    cudaGetSymbolAddress((void**)&p_x2,     g_x2);
    cudaGetSymbolAddress((void**)&p_h2,     g_h2);
    cudaGetSymbolAddress((void**)&p_gu,     g_gu);
    cudaGetSymbolAddress((void**)&p_act,    g_act);
    cudaGetSymbolAddress((void**)&p_he,     g_he);

    const int ATTN2_SMEM = ATTN2_FLOATS * 4;
    cudaFuncSetAttribute(attn_tc_kernel, cudaFuncAttributeMaxDynamicSharedMemorySize, ATTN2_SMEM);
    const int SM_P1 = 2 * 2 * MATS * 4;   // 73728 B
    const int SM_P3 = 2 * 4 * MATS * 4;   // 147456 B
    cudaFuncSetAttribute(gemm_cp<3,0>, cudaFuncAttributeMaxDynamicSharedMemorySize, SM_P3);
    cudaFuncSetAttribute(gemm_cp<3,1>, cudaFuncAttributeMaxDynamicSharedMemorySize, SM_P3);
    cudaFuncSetAttribute(gemm_cp<1,0>, cudaFuncAttributeMaxDynamicSharedMemorySize, SM_P1);
    cudaFuncSetAttribute(gemm_cp<1,1>, cudaFuncAttributeMaxDynamicSharedMemorySize, SM_P1);
    cudaFuncSetAttribute(gemm_cp<1,2>, cudaFuncAttributeMaxDynamicSharedMemorySize, SM_P1);
    cudaFuncSetAttribute(gemm_cp<1,3>, cudaFuncAttributeMaxDynamicSharedMemorySize, SM_P1);

    // weight splits (hi/lo) for routing-critical GEMMs
    pack_wq_kernel<<<1024, 256>>>(Wq, p_wq_hi, p_wq_lo);
    split_kernel<<<2048, 256>>>(Wkv, p_wkv_hi, p_wkv_lo);
    split_kernel<<<1024, 256>>>(Wo, p_wo_hi, p_wo_lo);

    // attention block (tf32 3-pass on routing-critical path)
    rmsnorm_kernel<1><<<TT, 256>>>(x, ln1, p_h_hi, p_h_lo);
    gemm_cp<3,0><<<dim3(8, 16), 256, SM_P3>>>(p_h_hi, p_h_lo, p_wq_hi, p_wq_lo,
                                              p_q, nullptr, 1024, 1024, 1024, 1024);
    gemm_cp<3,0><<<dim3(16,16), 256, SM_P3>>>(p_h_hi, p_h_lo, p_wkv_hi, p_wkv_lo,
                                              p_kv, nullptr, 1024, 1024, 1024, 2048);
    attn_tc_kernel<<<dim3(16, NH, 2), 256, ATTN2_SMEM>>>(p_q, p_kv, p_o_hi, p_o_lo);
    gemm_cp<3,1><<<dim3(8, 16), 256, SM_P3>>>(p_o_hi, p_o_lo, p_wo_hi, p_wo_lo,
                                              p_x2, x, 1024, 1024, 1024, 1024);

    // MoE block
    rmsnorm_kernel<0><<<TT, 256>>>(p_x2, ln2, p_h2, nullptr);
    gate_kernel<<<TT, 256>>>(p_h2, gate);
    route_group_kernel<<<1, 256>>>();
    gemm_cp<1,2><<<dim3(8, 32, NEXP), 256, SM_P1>>>(p_h2, nullptr, w1, nullptr,
                                                    nullptr, nullptr, 1024, 1024, 1024, 1024);
    gemm_cp<1,3><<<dim3(8, 32, NEXP), 256, SM_P1>>>(p_he, nullptr, w2, nullptr,
                                                    nullptr, nullptr, 1024, 1024, 1024, 1024);

    // shared expert
    gemm_cp<1,0><<<dim3(16,16), 256, SM_P1>>>(p_h2, nullptr, sgu, nullptr,
                                              p_gu, nullptr, 1024, 1024, 1024, 2048);
    swiglu_kernel<<<TT, 256>>>(p_gu, p_act);
    gemm_cp<1,1><<<dim3(8, 16), 256, SM_P1>>>(p_act, nullptr, sdwn, nullptr,
                                              out, p_x2, 1024, 1024, 1024, 1024);

    // combine routed experts
    add_routed_kernel<<<TT, 256>>>(out);
}